// round 4
// baseline (speedup 1.0000x reference)
#include <cuda_runtime.h>
#include <math.h>

#define NB 2048
#define NT 30
#define NACT 6
#define NSTOCH 64
#define NDETER 1024
#define NHID 1024
#define NOUT 1152          // 2*STOCH + DETER
#define LN_EPS 1e-5f

// Persistent state / scratch (allocation-free: __device__ globals)
__device__ float g_xh[NB * 2048];      // [B, 2048] = [ x (0..1023) | deter (1024..2047) ]
__device__ float g_parts[NB * 3072];   // GRU pre-LN parts
__device__ float g_h[NB * NHID];       // e1 hidden
__device__ float g_stats[NB * 128];    // e2 stats
__device__ float g_stoch[NB * NSTOCH]; // stoch state

__device__ __forceinline__ float elu1(float x) { return x > 0.f ? x : (expf(x) - 1.f); }
__device__ __forceinline__ float sigm(float x) { return 1.f / (1.f + expf(-x)); }
__device__ __forceinline__ float softplus1(float x) {
    return x > 0.f ? x + log1pf(expf(-x)) : log1pf(expf(x));
}

// Block-wide sum of (s, q). blockDim.x must be a multiple of 32 (here 256).
__device__ __forceinline__ void blk_red2(float& s, float& q, float* sh) {
    const unsigned m = 0xffffffffu;
    #pragma unroll
    for (int o = 16; o; o >>= 1) {
        s += __shfl_down_sync(m, s, o);
        q += __shfl_down_sync(m, q, o);
    }
    int w = threadIdx.x >> 5, l = threadIdx.x & 31;
    int nw = blockDim.x >> 5;
    if (l == 0) { sh[2 * w] = s; sh[2 * w + 1] = q; }
    __syncthreads();
    if (threadIdx.x == 0) {
        float ts = 0.f, tq = 0.f;
        for (int i = 0; i < nw; i++) { ts += sh[2 * i]; tq += sh[2 * i + 1]; }
        sh[0] = ts; sh[1] = tq;
    }
    __syncthreads();
    s = sh[0]; q = sh[1];
    __syncthreads();
}

__global__ void k_zero() {
    const long n1 = (long)NB * 2048;
    const long n = n1 + (long)NB * NSTOCH;
    for (long i = blockIdx.x * (long)blockDim.x + threadIdx.x; i < n;
         i += (long)gridDim.x * blockDim.x) {
        if (i < n1) g_xh[i] = 0.f;
        else g_stoch[i - n1] = 0.f;
    }
}

// x = ELU(LN(concat(stoch, a_t) @ W_img + b_img))  -> g_xh[:, 0:1024]
// one block per batch row, 256 threads, 4 cols each
__global__ void k_img(const float* __restrict__ action, const float* __restrict__ W,
                      const float* __restrict__ bias, const float* __restrict__ gamma,
                      const float* __restrict__ beta, int t) {
    __shared__ float sbuf[NSTOCH + NACT];
    __shared__ float red[16];
    const int b = blockIdx.x, tid = threadIdx.x;
    if (tid < NSTOCH) sbuf[tid] = g_stoch[b * NSTOCH + tid];
    else if (tid < NSTOCH + NACT) sbuf[tid] = action[((long)b * NT + t) * NACT + (tid - NSTOCH)];
    __syncthreads();

    float acc[4];
    #pragma unroll
    for (int i = 0; i < 4; i++) acc[i] = bias[tid + i * 256];
    for (int k = 0; k < NSTOCH + NACT; k++) {
        float s = sbuf[k];
        const float* Wk = W + (long)k * NHID;
        #pragma unroll
        for (int i = 0; i < 4; i++) acc[i] = fmaf(s, Wk[tid + i * 256], acc[i]);
    }
    float s = 0.f, q = 0.f;
    #pragma unroll
    for (int i = 0; i < 4; i++) { s += acc[i]; q += acc[i] * acc[i]; }
    blk_red2(s, q, red);
    float mean = s * (1.f / NHID);
    float var = q * (1.f / NHID) - mean * mean;
    float rstd = rsqrtf(var + LN_EPS);
    #pragma unroll
    for (int i = 0; i < 4; i++) {
        int c = tid + i * 256;
        float v = (acc[i] - mean) * rstd * gamma[c] + beta[c];
        g_xh[(long)b * 2048 + c] = elu1(v);
    }
}

// LN(parts) -> GRU gates -> new deter; writes deter into g_xh[:,1024:] and out[...,128:1152]
__global__ void k_gru(const float* __restrict__ gamma, const float* __restrict__ beta,
                      float* __restrict__ out, int t) {
    __shared__ float red[16];
    const int b = blockIdx.x, tid = threadIdx.x;
    const float* p = g_parts + (long)b * 3072;
    float v[12];
    float s = 0.f, q = 0.f;
    #pragma unroll
    for (int i = 0; i < 12; i++) {
        v[i] = p[tid + i * 256];
        s += v[i]; q += v[i] * v[i];
    }
    blk_red2(s, q, red);
    float mean = s * (1.f / 3072.f);
    float var = q * (1.f / 3072.f) - mean * mean;
    float rstd = rsqrtf(var + LN_EPS);
    float* outr = out + ((long)b * NT + t) * NOUT;
    #pragma unroll
    for (int i = 0; i < 4; i++) {
        int j = tid + i * 256;
        float r = (v[i]     - mean) * rstd * gamma[j]        + beta[j];
        float c = (v[i + 4] - mean) * rstd * gamma[1024 + j] + beta[1024 + j];
        float u = (v[i + 8] - mean) * rstd * gamma[2048 + j] + beta[2048 + j];
        r = sigm(r);
        c = tanhf(r * c);
        u = sigm(u - 1.f);           // UPDATE_BIAS = -1
        float dold = g_xh[(long)b * 2048 + 1024 + j];
        float d = u * c + (1.f - u) * dold;
        g_xh[(long)b * 2048 + 1024 + j] = d;
        outr[128 + j] = d;
    }
}

// h = ELU(LN(h_pre))  in place on g_h, ensemble-0 gamma/beta
__global__ void k_lnelu(const float* __restrict__ gamma, const float* __restrict__ beta) {
    __shared__ float red[16];
    const int b = blockIdx.x, tid = threadIdx.x;
    float* h = g_h + (long)b * NHID;
    float v[4];
    float s = 0.f, q = 0.f;
    #pragma unroll
    for (int i = 0; i < 4; i++) {
        v[i] = h[tid + i * 256];
        s += v[i]; q += v[i] * v[i];
    }
    blk_red2(s, q, red);
    float mean = s * (1.f / NHID);
    float var = q * (1.f / NHID) - mean * mean;
    float rstd = rsqrtf(var + LN_EPS);
    #pragma unroll
    for (int i = 0; i < 4; i++) {
        int c = tid + i * 256;
        h[c] = elu1((v[i] - mean) * rstd * gamma[c] + beta[c]);
    }
}

// stats -> stoch (mean), std (softplus+0.1); writes out[..., 0:128] and g_stoch
__global__ void k_stats(float* __restrict__ out, int t) {
    int idx = blockIdx.x * blockDim.x + threadIdx.x;
    if (idx >= NB * NSTOCH) return;
    int b = idx / NSTOCH, s = idx % NSTOCH;
    float mean = g_stats[b * 128 + s];
    float sr = g_stats[b * 128 + 64 + s];
    float std = softplus1(sr) + 0.1f;
    g_stoch[idx] = mean;
    float* outr = out + ((long)b * NT + t) * NOUT;
    outr[s] = mean;
    outr[64 + s] = std;
}

// Tiled SGEMM: C[M,N] = A[M,K] @ B[K,N] + bias[N].
// (BM/TM)*(BN/TN) == 256 threads, BM*BK == BK*BN == 1024 (one float4 per thread per tile).
template <int BM, int BN, int BK, int TM, int TN>
__global__ void gemm(const float* __restrict__ A, int lda,
                     const float* __restrict__ Bm, int ldb,
                     const float* __restrict__ bias,
                     float* __restrict__ C, int ldc, int K) {
    __shared__ float As[BK][BM];
    __shared__ float Bs[BK][BN];
    constexpr int TX = BN / TN;
    const int tid = threadIdx.x;
    const int row0 = blockIdx.y * BM, col0 = blockIdx.x * BN;
    const int ty = tid / TX, tx = tid % TX;

    const int a_idx = tid * 4;
    const int a_row = a_idx / BK, a_col = a_idx % BK;
    const int b_idx = tid * 4;
    const int b_row = b_idx / BN, b_col = b_idx % BN;

    const float* Aptr = A + (long)(row0 + a_row) * lda + a_col;
    const float* Bptr = Bm + (long)b_row * ldb + col0 + b_col;

    float4 av = *(const float4*)Aptr;
    float4 bv = *(const float4*)Bptr;

    float acc[TM][TN];
    #pragma unroll
    for (int i = 0; i < TM; i++)
        #pragma unroll
        for (int j = 0; j < TN; j++) acc[i][j] = 0.f;

    for (int k0 = 0; k0 < K; k0 += BK) {
        As[a_col + 0][a_row] = av.x;
        As[a_col + 1][a_row] = av.y;
        As[a_col + 2][a_row] = av.z;
        As[a_col + 3][a_row] = av.w;
        *(float4*)&Bs[b_row][b_col] = bv;
        __syncthreads();
        if (k0 + BK < K) {
            av = *(const float4*)(Aptr + k0 + BK);
            bv = *(const float4*)(Bptr + (long)(k0 + BK) * ldb);
        }
        #pragma unroll
        for (int k = 0; k < BK; k++) {
            float a[TM], bb[TN];
            #pragma unroll
            for (int i = 0; i < TM; i++) a[i] = As[k][ty * TM + i];
            #pragma unroll
            for (int j = 0; j < TN; j++) bb[j] = Bs[k][tx * TN + j];
            #pragma unroll
            for (int i = 0; i < TM; i++)
                #pragma unroll
                for (int j = 0; j < TN; j++) acc[i][j] = fmaf(a[i], bb[j], acc[i][j]);
        }
        __syncthreads();
    }
    #pragma unroll
    for (int i = 0; i < TM; i++) {
        float* Crow = C + (long)(row0 + ty * TM + i) * ldc + col0 + tx * TN;
        #pragma unroll
        for (int j = 0; j < TN; j++) Crow[j] = acc[i][j] + bias[col0 + tx * TN + j];
    }
}

extern "C" void kernel_launch(void* const* d_in, const int* in_sizes, int n_in,
                              void* d_out, int out_size) {
    const float* action   = (const float*)d_in[0];
    const float* W_img    = (const float*)d_in[1];
    const float* b_img    = (const float*)d_in[2];
    const float* gi       = (const float*)d_in[3];
    const float* bei      = (const float*)d_in[4];
    const float* W_gru    = (const float*)d_in[5];
    const float* b_gru    = (const float*)d_in[6];
    const float* gg       = (const float*)d_in[7];
    const float* beg      = (const float*)d_in[8];
    const float* W_e1     = (const float*)d_in[9];   // [5,1024,1024]; use slice 0
    const float* b_e1     = (const float*)d_in[10];  // [5,1024]; use slice 0
    const float* ge1      = (const float*)d_in[11];
    const float* bee1     = (const float*)d_in[12];
    const float* W_e2     = (const float*)d_in[13];  // [5,1024,128]; use slice 0
    const float* b_e2     = (const float*)d_in[14];  // [5,128]; use slice 0
    float* out = (float*)d_out;

    void *p_xh, *p_parts, *p_h, *p_stats;
    cudaGetSymbolAddress(&p_xh, g_xh);
    cudaGetSymbolAddress(&p_parts, g_parts);
    cudaGetSymbolAddress(&p_h, g_h);
    cudaGetSymbolAddress(&p_stats, g_stats);
    float* xh = (float*)p_xh;
    float* parts = (float*)p_parts;
    float* h = (float*)p_h;
    float* stats = (float*)p_stats;

    k_zero<<<256, 256>>>();

    const dim3 g_gru_gemm(3072 / 128, 2048 / 128);  // 24 x 16
    const dim3 g_e1_gemm(1024 / 128, 2048 / 128);   //  8 x 16
    const dim3 g_e2_gemm(128 / 32, 2048 / 32);      //  4 x 64

    for (int t = 0; t < NT; t++) {
        // 1. img linear + LN + ELU -> xh[:, 0:1024]
        k_img<<<NB, 256>>>(action, W_img, b_img, gi, bei, t);
        // 2. GRU GEMM: parts_pre = xh[2048x2048] @ W_gru[2048x3072] + b_gru
        gemm<128, 128, 8, 8, 8><<<g_gru_gemm, 256>>>(xh, 2048, W_gru, 3072, b_gru,
                                                     parts, 3072, 2048);
        // 3. LN + GRU gates -> deter (xh[:,1024:]) and out deter slice
        k_gru<<<NB, 256>>>(gg, beg, out, t);
        // 4. e1 GEMM: h_pre = deter[2048x1024] @ W_e1[0][1024x1024] + b_e1[0]
        gemm<128, 128, 8, 8, 8><<<g_e1_gemm, 256>>>(xh + 1024, 2048, W_e1, 1024, b_e1,
                                                    h, 1024, 1024);
        // 5. LN + ELU on h
        k_lnelu<<<NB, 256>>>(ge1, bee1);
        // 6. e2 GEMM: stats = h[2048x1024] @ W_e2[0][1024x128] + b_e2[0]
        gemm<32, 32, 32, 2, 2><<<g_e2_gemm, 256>>>(h, 1024, W_e2, 128, b_e2,
                                                   stats, 128, 1024);
        // 7. stoch/std epilogue
        k_stats<<<(NB * NSTOCH + 255) / 256, 256>>>(out, t);
    }
    (void)in_sizes; (void)n_in; (void)out_size;
}

// round 7
// speedup vs baseline: 1.9600x; 1.9600x over previous
#include <cuda_runtime.h>
#include <cuda_bf16.h>
#include <math.h>
#include <stdint.h>

#define NB 2048
#define NT 30
#define NACT 6
#define NSTOCH 64
#define NDETER 1024
#define NHID 1024
#define NOUT 1152
#define LN_EPS 1e-5f

// GEMM tiling
#define BMT 128
#define BNT 128
#define BKT 64
#define ROWB 144                       // 64 bf16 = 128B + 16B pad
#define STAGE_BYTES (128 * ROWB * 2)   // A tile + B tile = 36864
#define NSTG 3
#define SMEM_SZ (NSTG * STAGE_BYTES)   // 110592

// ---------------- persistent buffers ----------------
__device__ float g_xh[NB * 2048];      // fp32 [x | deter] (deter half used by k_gru)
__device__ float g_parts[NB * 3072];
__device__ float g_h[NB * NHID];
__device__ float g_stats[NB * 128];
__device__ float g_stoch[NB * NSTOCH];

__device__ __align__(16) __nv_bfloat16 g_xh_hi[NB * 2048];   // A of GRU (and e1 via col offset)
__device__ __align__(16) __nv_bfloat16 g_xh_lo[NB * 2048];
__device__ __align__(16) __nv_bfloat16 g_h_hi[NB * NHID];    // A of e2
__device__ __align__(16) __nv_bfloat16 g_h_lo[NB * NHID];
__device__ __align__(16) __nv_bfloat16 g_wg_hi[3072 * 2048]; // W_gru^T [N,K]
__device__ __align__(16) __nv_bfloat16 g_wg_lo[3072 * 2048];
__device__ __align__(16) __nv_bfloat16 g_we1_hi[1024 * 1024];
__device__ __align__(16) __nv_bfloat16 g_we1_lo[1024 * 1024];
__device__ __align__(16) __nv_bfloat16 g_we2_hi[128 * 1024];
__device__ __align__(16) __nv_bfloat16 g_we2_lo[128 * 1024];

// ---------------- helpers ----------------
__device__ __forceinline__ float elu1(float x) { return x > 0.f ? x : (expf(x) - 1.f); }
__device__ __forceinline__ float sigm(float x) { return 1.f / (1.f + expf(-x)); }
__device__ __forceinline__ float softplus1(float x) {
    return x > 0.f ? x + log1pf(expf(-x)) : log1pf(expf(x));
}
__device__ __forceinline__ void split_store(__nv_bfloat16* hi, __nv_bfloat16* lo,
                                            size_t idx, float v) {
    __nv_bfloat16 h = __float2bfloat16(v);
    hi[idx] = h;
    lo[idx] = __float2bfloat16(v - __bfloat162float(h));
}
__device__ __forceinline__ uint32_t smem_u32(const void* p) {
    uint32_t a;
    asm("{ .reg .u64 t; cvta.to.shared.u64 t, %1; cvt.u32.u64 %0, t; }" : "=r"(a) : "l"(p));
    return a;
}
__device__ __forceinline__ void cp16(uint32_t s, const void* g) {
    asm volatile("cp.async.cg.shared.global [%0], [%1], 16;" :: "r"(s), "l"(g));
}
__device__ __forceinline__ void ldsm4(uint32_t* r, uint32_t addr) {
    asm volatile("ldmatrix.sync.aligned.m8n8.x4.shared.b16 {%0,%1,%2,%3}, [%4];"
        : "=r"(r[0]), "=r"(r[1]), "=r"(r[2]), "=r"(r[3]) : "r"(addr));
}
__device__ __forceinline__ void mma16816(float* d, const uint32_t* a, const uint32_t* b) {
    asm volatile("mma.sync.aligned.m16n8k16.row.col.f32.bf16.bf16.f32 "
        "{%0,%1,%2,%3}, {%4,%5,%6,%7}, {%8,%9}, {%0,%1,%2,%3};"
        : "+f"(d[0]), "+f"(d[1]), "+f"(d[2]), "+f"(d[3])
        : "r"(a[0]), "r"(a[1]), "r"(a[2]), "r"(a[3]), "r"(b[0]), "r"(b[1]));
}
#define CP_COMMIT() asm volatile("cp.async.commit_group;" ::: "memory")
#define CP_WAIT1()  asm volatile("cp.async.wait_group 1;" ::: "memory")

// ---------------- reductions ----------------
__device__ __forceinline__ void blk_red2(float& s, float& q, float* sh) {
    const unsigned m = 0xffffffffu;
    #pragma unroll
    for (int o = 16; o; o >>= 1) {
        s += __shfl_down_sync(m, s, o);
        q += __shfl_down_sync(m, q, o);
    }
    int w = threadIdx.x >> 5, l = threadIdx.x & 31;
    int nw = blockDim.x >> 5;
    if (l == 0) { sh[2 * w] = s; sh[2 * w + 1] = q; }
    __syncthreads();
    if (threadIdx.x == 0) {
        float ts = 0.f, tq = 0.f;
        for (int i = 0; i < nw; i++) { ts += sh[2 * i]; tq += sh[2 * i + 1]; }
        sh[0] = ts; sh[1] = tq;
    }
    __syncthreads();
    s = sh[0]; q = sh[1];
    __syncthreads();
}

// ---------------- init / weight transpose+split ----------------
__global__ void k_zero() {
    long i0 = blockIdx.x * (long)blockDim.x + threadIdx.x;
    long stride = (long)gridDim.x * blockDim.x;
    for (long i = i0; i < (long)NB * 2048; i += stride) g_xh[i] = 0.f;
    for (long i = i0; i < (long)NB * NSTOCH; i += stride) g_stoch[i] = 0.f;
    unsigned short* hi = (unsigned short*)g_xh_hi;
    unsigned short* lo = (unsigned short*)g_xh_lo;
    for (long i = i0; i < (long)NB * 2048; i += stride) { hi[i] = 0; lo[i] = 0; }
}

// W [K,N] fp32 -> Wt hi/lo [N,K] bf16, coalesced both ways via smem tile
__global__ void wtrans(const float* __restrict__ W, __nv_bfloat16* __restrict__ hi,
                       __nv_bfloat16* __restrict__ lo, int K, int N) {
    __shared__ float s[32][33];
    int k0 = blockIdx.y * 32, n0 = blockIdx.x * 32;
    int tx = threadIdx.x, ty = threadIdx.y;
    #pragma unroll
    for (int j = 0; j < 4; j++)
        s[ty + j * 8][tx] = W[(size_t)(k0 + ty + j * 8) * N + n0 + tx];
    __syncthreads();
    #pragma unroll
    for (int j = 0; j < 4; j++) {
        int n = n0 + ty + j * 8, k = k0 + tx;
        split_store(hi, lo, (size_t)n * K + k, s[tx][ty + j * 8]);
    }
}

// ---------------- fused pointwise kernels ----------------
__global__ void k_img(const float* __restrict__ action, const float* __restrict__ W,
                      const float* __restrict__ bias, const float* __restrict__ gamma,
                      const float* __restrict__ beta, int t) {
    __shared__ float sbuf[NSTOCH + NACT];
    __shared__ float red[16];
    const int b = blockIdx.x, tid = threadIdx.x;
    if (tid < NSTOCH) sbuf[tid] = g_stoch[b * NSTOCH + tid];
    else if (tid < NSTOCH + NACT) sbuf[tid] = action[((long)b * NT + t) * NACT + (tid - NSTOCH)];
    __syncthreads();

    float acc[4];
    #pragma unroll
    for (int i = 0; i < 4; i++) acc[i] = bias[tid + i * 256];
    for (int k = 0; k < NSTOCH + NACT; k++) {
        float s = sbuf[k];
        const float* Wk = W + (long)k * NHID;
        #pragma unroll
        for (int i = 0; i < 4; i++) acc[i] = fmaf(s, Wk[tid + i * 256], acc[i]);
    }
    float s = 0.f, q = 0.f;
    #pragma unroll
    for (int i = 0; i < 4; i++) { s += acc[i]; q += acc[i] * acc[i]; }
    blk_red2(s, q, red);
    float mean = s * (1.f / NHID);
    float var = q * (1.f / NHID) - mean * mean;
    float rstd = rsqrtf(var + LN_EPS);
    #pragma unroll
    for (int i = 0; i < 4; i++) {
        int c = tid + i * 256;
        float v = elu1((acc[i] - mean) * rstd * gamma[c] + beta[c]);
        split_store(g_xh_hi, g_xh_lo, (size_t)b * 2048 + c, v);
    }
}

__global__ void k_gru(const float* __restrict__ gamma, const float* __restrict__ beta,
                      float* __restrict__ out, int t) {
    __shared__ float red[16];
    const int b = blockIdx.x, tid = threadIdx.x;
    const float* p = g_parts + (long)b * 3072;
    float v[12];
    float s = 0.f, q = 0.f;
    #pragma unroll
    for (int i = 0; i < 12; i++) {
        v[i] = p[tid + i * 256];
        s += v[i]; q += v[i] * v[i];
    }
    blk_red2(s, q, red);
    float mean = s * (1.f / 3072.f);
    float var = q * (1.f / 3072.f) - mean * mean;
    float rstd = rsqrtf(var + LN_EPS);
    float* outr = out + ((long)b * NT + t) * NOUT;
    #pragma unroll
    for (int i = 0; i < 4; i++) {
        int j = tid + i * 256;
        float r = (v[i]     - mean) * rstd * gamma[j]        + beta[j];
        float c = (v[i + 4] - mean) * rstd * gamma[1024 + j] + beta[1024 + j];
        float u = (v[i + 8] - mean) * rstd * gamma[2048 + j] + beta[2048 + j];
        r = sigm(r);
        c = tanhf(r * c);
        u = sigm(u - 1.f);
        float dold = g_xh[(long)b * 2048 + 1024 + j];
        float d = u * c + (1.f - u) * dold;
        g_xh[(long)b * 2048 + 1024 + j] = d;
        outr[128 + j] = d;
        split_store(g_xh_hi, g_xh_lo, (size_t)b * 2048 + 1024 + j, d);
    }
}

__global__ void k_lnelu(const float* __restrict__ gamma, const float* __restrict__ beta) {
    __shared__ float red[16];
    const int b = blockIdx.x, tid = threadIdx.x;
    const float* h = g_h + (long)b * NHID;
    float v[4];
    float s = 0.f, q = 0.f;
    #pragma unroll
    for (int i = 0; i < 4; i++) {
        v[i] = h[tid + i * 256];
        s += v[i]; q += v[i] * v[i];
    }
    blk_red2(s, q, red);
    float mean = s * (1.f / NHID);
    float var = q * (1.f / NHID) - mean * mean;
    float rstd = rsqrtf(var + LN_EPS);
    #pragma unroll
    for (int i = 0; i < 4; i++) {
        int c = tid + i * 256;
        float val = elu1((v[i] - mean) * rstd * gamma[c] + beta[c]);
        split_store(g_h_hi, g_h_lo, (size_t)b * NHID + c, val);
    }
}

__global__ void k_stats(float* __restrict__ out, int t) {
    int idx = blockIdx.x * blockDim.x + threadIdx.x;
    if (idx >= NB * NSTOCH) return;
    int b = idx / NSTOCH, s = idx % NSTOCH;
    float mean = g_stats[b * 128 + s];
    float sr = g_stats[b * 128 + 64 + s];
    float std = softplus1(sr) + 0.1f;
    g_stoch[idx] = mean;
    float* outr = out + ((long)b * NT + t) * NOUT;
    outr[s] = mean;
    outr[64 + s] = std;
}

// ---------------- HMMA bf16x3 GEMM ----------------
// C[M,N] = sum3phases( A(hi/lo)[M,K] @ Bt(hi/lo)[N,K]^T ) + bias
__global__ void __launch_bounds__(256, 1) gemm_hmma(
    const __nv_bfloat16* __restrict__ Ahi, const __nv_bfloat16* __restrict__ Alo,
    int lda, int K,
    const __nv_bfloat16* __restrict__ Bhi, const __nv_bfloat16* __restrict__ Blo,
    const float* __restrict__ bias, float* __restrict__ C, int ldc) {
    extern __shared__ char smem[];
    const int tid = threadIdx.x, lid = tid & 31, wid = tid >> 5;
    const int wm = wid & 1, wn = wid >> 1;          // 2 x 4 warp grid
    const int bx = blockIdx.x, by = blockIdx.y;
    const uint32_t sbase = smem_u32(smem);

    const int kpp = K >> 6;        // 64-wide chunks per phase
    const int NC = 3 * kpp;

    // ldmatrix per-lane offsets
    const int lr = lid & 7, sub = lid >> 3;
    const uint32_t a_off = (uint32_t)((wm * 64 + (sub & 1) * 8 + lr) * ROWB
                                      + ((sub >> 1) * 8) * 2);
    const uint32_t b_off0 = (uint32_t)((wn * 32 + (sub >> 1) * 8 + lr) * ROWB
                                       + ((sub & 1) * 8) * 2);
    const uint32_t b_off1 = b_off0 + 16 * ROWB;

    float acc[4][4][4];
    #pragma unroll
    for (int i = 0; i < 4; i++)
        #pragma unroll
        for (int j = 0; j < 4; j++)
            #pragma unroll
            for (int k = 0; k < 4; k++) acc[i][j][k] = 0.f;

    auto issue = [&](int cc, int stg) {
        int p = cc / kpp, j = cc - p * kpp, k0 = j << 6;
        const __nv_bfloat16* As = (p == 1) ? Alo : Ahi;
        const __nv_bfloat16* Bs = (p == 2) ? Blo : Bhi;
        uint32_t sa = sbase + stg * STAGE_BYTES;
        uint32_t sb = sa + 128 * ROWB;
        #pragma unroll
        for (int i = 0; i < 4; i++) {
            int c = tid + i * 256, r = c >> 3, sg = c & 7;
            cp16(sa + r * ROWB + sg * 16, As + (size_t)(by * BMT + r) * lda + k0 + sg * 8);
            cp16(sb + r * ROWB + sg * 16, Bs + (size_t)(bx * BNT + r) * K + k0 + sg * 8);
        }
    };

    issue(0, 0); CP_COMMIT();
    issue(1, 1); CP_COMMIT();

    for (int cc = 0; cc < NC; cc++) {
        CP_WAIT1();
        __syncthreads();
        int cp = cc + 2;
        if (cp < NC) issue(cp, cp % NSTG);
        CP_COMMIT();

        uint32_t sa = sbase + (cc % NSTG) * STAGE_BYTES;
        uint32_t sb = sa + 128 * ROWB;
        #pragma unroll
        for (int ks = 0; ks < 4; ks++) {
            uint32_t afr[4][4], bfr[2][4];
            ldsm4(bfr[0], sb + b_off0 + ks * 32);
            ldsm4(bfr[1], sb + b_off1 + ks * 32);
            #pragma unroll
            for (int mi = 0; mi < 4; mi++)
                ldsm4(afr[mi], sa + a_off + mi * (16 * ROWB) + ks * 32);
            #pragma unroll
            for (int mi = 0; mi < 4; mi++)
                #pragma unroll
                for (int ni = 0; ni < 4; ni++)
                    mma16816(acc[mi][ni], afr[mi], &bfr[ni >> 1][(ni & 1) * 2]);
        }
    }

    // epilogue
    const int row_base = by * BMT + wm * 64 + (lid >> 2);
    const int col_base = bx * BNT + wn * 32 + (lid & 3) * 2;
    #pragma unroll
    for (int ni = 0; ni < 4; ni++) {
        int cg = col_base + ni * 8;
        float b0 = bias[cg], b1 = bias[cg + 1];
        #pragma unroll
        for (int mi = 0; mi < 4; mi++) {
            int r = row_base + mi * 16;
            float2 v0 = { acc[mi][ni][0] + b0, acc[mi][ni][1] + b1 };
            float2 v1 = { acc[mi][ni][2] + b0, acc[mi][ni][3] + b1 };
            *(float2*)(C + (size_t)r * ldc + cg) = v0;
            *(float2*)(C + (size_t)(r + 8) * ldc + cg) = v1;
        }
    }
}

// ---------------- launcher ----------------
extern "C" void kernel_launch(void* const* d_in, const int* in_sizes, int n_in,
                              void* d_out, int out_size) {
    const float* action = (const float*)d_in[0];
    const float* W_img  = (const float*)d_in[1];
    const float* b_img  = (const float*)d_in[2];
    const float* gi     = (const float*)d_in[3];
    const float* bei    = (const float*)d_in[4];
    const float* W_gru  = (const float*)d_in[5];
    const float* b_gru  = (const float*)d_in[6];
    const float* gg     = (const float*)d_in[7];
    const float* beg    = (const float*)d_in[8];
    const float* W_e1   = (const float*)d_in[9];
    const float* b_e1   = (const float*)d_in[10];
    const float* ge1    = (const float*)d_in[11];
    const float* bee1   = (const float*)d_in[12];
    const float* W_e2   = (const float*)d_in[13];
    const float* b_e2   = (const float*)d_in[14];
    float* out = (float*)d_out;

    void *p_parts, *p_h, *p_stats, *p_xh_hi, *p_xh_lo, *p_h_hi, *p_h_lo;
    void *p_wg_hi, *p_wg_lo, *p_we1_hi, *p_we1_lo, *p_we2_hi, *p_we2_lo;
    cudaGetSymbolAddress(&p_parts, g_parts);
    cudaGetSymbolAddress(&p_h, g_h);
    cudaGetSymbolAddress(&p_stats, g_stats);
    cudaGetSymbolAddress(&p_xh_hi, g_xh_hi);
    cudaGetSymbolAddress(&p_xh_lo, g_xh_lo);
    cudaGetSymbolAddress(&p_h_hi, g_h_hi);
    cudaGetSymbolAddress(&p_h_lo, g_h_lo);
    cudaGetSymbolAddress(&p_wg_hi, g_wg_hi);
    cudaGetSymbolAddress(&p_wg_lo, g_wg_lo);
    cudaGetSymbolAddress(&p_we1_hi, g_we1_hi);
    cudaGetSymbolAddress(&p_we1_lo, g_we1_lo);
    cudaGetSymbolAddress(&p_we2_hi, g_we2_hi);
    cudaGetSymbolAddress(&p_we2_lo, g_we2_lo);

    cudaFuncSetAttribute(gemm_hmma, cudaFuncAttributeMaxDynamicSharedMemorySize, SMEM_SZ);

    k_zero<<<512, 256>>>();
    wtrans<<<dim3(3072 / 32, 2048 / 32), dim3(32, 8)>>>(
        W_gru, (__nv_bfloat16*)p_wg_hi, (__nv_bfloat16*)p_wg_lo, 2048, 3072);
    wtrans<<<dim3(1024 / 32, 1024 / 32), dim3(32, 8)>>>(
        W_e1, (__nv_bfloat16*)p_we1_hi, (__nv_bfloat16*)p_we1_lo, 1024, 1024);
    wtrans<<<dim3(128 / 32, 1024 / 32), dim3(32, 8)>>>(
        W_e2, (__nv_bfloat16*)p_we2_hi, (__nv_bfloat16*)p_we2_lo, 1024, 128);

    const dim3 g_gru(3072 / BNT, 2048 / BMT);  // 24 x 16
    const dim3 g_e1(1024 / BNT, 2048 / BMT);   //  8 x 16
    const dim3 g_e2(128 / BNT, 2048 / BMT);    //  1 x 16

    for (int t = 0; t < NT; t++) {
        k_img<<<NB, 256>>>(action, W_img, b_img, gi, bei, t);
        gemm_hmma<<<g_gru, 256, SMEM_SZ>>>(
            (__nv_bfloat16*)p_xh_hi, (__nv_bfloat16*)p_xh_lo, 2048, 2048,
            (__nv_bfloat16*)p_wg_hi, (__nv_bfloat16*)p_wg_lo,
            b_gru, (float*)p_parts, 3072);
        k_gru<<<NB, 256>>>(gg, beg, out, t);
        gemm_hmma<<<g_e1, 256, SMEM_SZ>>>(
            (__nv_bfloat16*)p_xh_hi + 1024, (__nv_bfloat16*)p_xh_lo + 1024, 2048, 1024,
            (__nv_bfloat16*)p_we1_hi, (__nv_bfloat16*)p_we1_lo,
            b_e1, (float*)p_h, 1024);
        k_lnelu<<<NB, 256>>>(ge1, bee1);
        gemm_hmma<<<g_e2, 256, SMEM_SZ>>>(
            (__nv_bfloat16*)p_h_hi, (__nv_bfloat16*)p_h_lo, 1024, 1024,
            (__nv_bfloat16*)p_we2_hi, (__nv_bfloat16*)p_we2_lo,
            b_e2, (float*)p_stats, 128);
        k_stats<<<(NB * NSTOCH + 255) / 256, 256>>>(out, t);
    }
    (void)in_sizes; (void)n_in; (void)out_size;
}

// round 8
// speedup vs baseline: 2.1229x; 1.0831x over previous
#include <cuda_runtime.h>
#include <cuda_bf16.h>
#include <math.h>
#include <stdint.h>

#define NB 2048
#define NT 30
#define NACT 6
#define NSTOCH 64
#define NDETER 1024
#define NHID 1024
#define NOUT 1152
#define LN_EPS 1e-5f

// GEMM tiling
#define BMT 128
#define BNT 128
#define ROWB 144                       // 64 bf16 = 128B + 16B pad
#define STAGE_BYTES (128 * ROWB * 2)   // A tile + B tile = 36864
#define NSTG 3
#define SMEM_SZ (NSTG * STAGE_BYTES)   // 110592

#define E2_SPLITS 8

// ---------------- persistent buffers ----------------
__device__ float g_xh[NB * 2048];      // fp32 [x | deter] (deter half used by k_gru)
__device__ float g_parts[NB * 3072];
__device__ float g_h[NB * NHID];
__device__ float g_stats_part[E2_SPLITS * NB * 128];
__device__ float g_stoch[NB * NSTOCH];

__device__ __align__(16) __nv_bfloat16 g_xh_hi[NB * 2048];
__device__ __align__(16) __nv_bfloat16 g_xh_lo[NB * 2048];
__device__ __align__(16) __nv_bfloat16 g_h_hi[NB * NHID];
__device__ __align__(16) __nv_bfloat16 g_h_lo[NB * NHID];
__device__ __align__(16) __nv_bfloat16 g_wg_hi[3072 * 2048];
__device__ __align__(16) __nv_bfloat16 g_wg_lo[3072 * 2048];
__device__ __align__(16) __nv_bfloat16 g_we1_hi[1024 * 1024];
__device__ __align__(16) __nv_bfloat16 g_we1_lo[1024 * 1024];
__device__ __align__(16) __nv_bfloat16 g_we2_hi[128 * 1024];
__device__ __align__(16) __nv_bfloat16 g_we2_lo[128 * 1024];

// ---------------- helpers ----------------
__device__ __forceinline__ float elu1(float x) { return x > 0.f ? x : (expf(x) - 1.f); }
__device__ __forceinline__ float sigm(float x) { return 1.f / (1.f + expf(-x)); }
__device__ __forceinline__ float softplus1(float x) {
    return x > 0.f ? x + log1pf(expf(-x)) : log1pf(expf(x));
}
__device__ __forceinline__ void split_store(__nv_bfloat16* hi, __nv_bfloat16* lo,
                                            size_t idx, float v) {
    __nv_bfloat16 h = __float2bfloat16(v);
    hi[idx] = h;
    lo[idx] = __float2bfloat16(v - __bfloat162float(h));
}
__device__ __forceinline__ uint32_t smem_u32(const void* p) {
    uint32_t a;
    asm("{ .reg .u64 t; cvta.to.shared.u64 t, %1; cvt.u32.u64 %0, t; }" : "=r"(a) : "l"(p));
    return a;
}
__device__ __forceinline__ void cp16(uint32_t s, const void* g) {
    asm volatile("cp.async.cg.shared.global [%0], [%1], 16;" :: "r"(s), "l"(g));
}
__device__ __forceinline__ void ldsm4(uint32_t* r, uint32_t addr) {
    asm volatile("ldmatrix.sync.aligned.m8n8.x4.shared.b16 {%0,%1,%2,%3}, [%4];"
        : "=r"(r[0]), "=r"(r[1]), "=r"(r[2]), "=r"(r[3]) : "r"(addr));
}
__device__ __forceinline__ void mma16816(float* d, const uint32_t* a, const uint32_t* b) {
    asm volatile("mma.sync.aligned.m16n8k16.row.col.f32.bf16.bf16.f32 "
        "{%0,%1,%2,%3}, {%4,%5,%6,%7}, {%8,%9}, {%0,%1,%2,%3};"
        : "+f"(d[0]), "+f"(d[1]), "+f"(d[2]), "+f"(d[3])
        : "r"(a[0]), "r"(a[1]), "r"(a[2]), "r"(a[3]), "r"(b[0]), "r"(b[1]));
}
#define CP_COMMIT() asm volatile("cp.async.commit_group;" ::: "memory")
#define CP_WAIT1()  asm volatile("cp.async.wait_group 1;" ::: "memory")

// ---------------- reductions ----------------
__device__ __forceinline__ void blk_red2(float& s, float& q, float* sh) {
    const unsigned m = 0xffffffffu;
    #pragma unroll
    for (int o = 16; o; o >>= 1) {
        s += __shfl_down_sync(m, s, o);
        q += __shfl_down_sync(m, q, o);
    }
    int w = threadIdx.x >> 5, l = threadIdx.x & 31;
    int nw = blockDim.x >> 5;
    if (l == 0) { sh[2 * w] = s; sh[2 * w + 1] = q; }
    __syncthreads();
    if (threadIdx.x == 0) {
        float ts = 0.f, tq = 0.f;
        for (int i = 0; i < nw; i++) { ts += sh[2 * i]; tq += sh[2 * i + 1]; }
        sh[0] = ts; sh[1] = tq;
    }
    __syncthreads();
    s = sh[0]; q = sh[1];
    __syncthreads();
}

// ---------------- init / weight transpose+split ----------------
__global__ void k_zero() {
    long i0 = blockIdx.x * (long)blockDim.x + threadIdx.x;
    long stride = (long)gridDim.x * blockDim.x;
    for (long i = i0; i < (long)NB * 2048; i += stride) g_xh[i] = 0.f;
    for (long i = i0; i < (long)NB * NSTOCH; i += stride) g_stoch[i] = 0.f;
    unsigned short* hi = (unsigned short*)g_xh_hi;
    unsigned short* lo = (unsigned short*)g_xh_lo;
    for (long i = i0; i < (long)NB * 2048; i += stride) { hi[i] = 0; lo[i] = 0; }
}

__global__ void wtrans(const float* __restrict__ W, __nv_bfloat16* __restrict__ hi,
                       __nv_bfloat16* __restrict__ lo, int K, int N) {
    __shared__ float s[32][33];
    int k0 = blockIdx.y * 32, n0 = blockIdx.x * 32;
    int tx = threadIdx.x, ty = threadIdx.y;
    #pragma unroll
    for (int j = 0; j < 4; j++)
        s[ty + j * 8][tx] = W[(size_t)(k0 + ty + j * 8) * N + n0 + tx];
    __syncthreads();
    #pragma unroll
    for (int j = 0; j < 4; j++) {
        int n = n0 + ty + j * 8, k = k0 + tx;
        split_store(hi, lo, (size_t)n * K + k, s[tx][ty + j * 8]);
    }
}

// ---------------- fused pointwise kernels ----------------
// 16 batch rows per block; W streamed once per block (L2 traffic /16 vs 1-row version)
#define IMG_ROWS 16
__global__ void __launch_bounds__(256) k_img(
    const float* __restrict__ action, const float* __restrict__ W,
    const float* __restrict__ bias, const float* __restrict__ gamma,
    const float* __restrict__ beta, int t) {
    __shared__ float sbuf[IMG_ROWS][72];   // 70 inputs per row, padded
    __shared__ float red[IMG_ROWS][8][2];
    const int b0 = blockIdx.x * IMG_ROWS, tid = threadIdx.x;
    const int wid = tid >> 5, lid = tid & 31;

    for (int idx = tid; idx < IMG_ROWS * 70; idx += 256) {
        int r = idx / 70, k = idx % 70;
        float v = (k < NSTOCH) ? g_stoch[(b0 + r) * NSTOCH + k]
                               : action[((long)(b0 + r) * NT + t) * NACT + (k - NSTOCH)];
        sbuf[r][k] = v;
    }
    __syncthreads();

    float acc[IMG_ROWS][4];
    {
        float bz[4];
        #pragma unroll
        for (int i = 0; i < 4; i++) bz[i] = bias[tid + i * 256];
        #pragma unroll
        for (int r = 0; r < IMG_ROWS; r++)
            #pragma unroll
            for (int i = 0; i < 4; i++) acc[r][i] = bz[i];
    }
    // prefetch-next W row pattern
    float w[4], wn[4];
    #pragma unroll
    for (int i = 0; i < 4; i++) w[i] = W[tid + i * 256];
    for (int k = 0; k < 70; k++) {
        if (k + 1 < 70) {
            const float* Wk = W + (long)(k + 1) * NHID;
            #pragma unroll
            for (int i = 0; i < 4; i++) wn[i] = Wk[tid + i * 256];
        }
        #pragma unroll
        for (int r = 0; r < IMG_ROWS; r++) {
            float s = sbuf[r][k];
            #pragma unroll
            for (int i = 0; i < 4; i++) acc[r][i] = fmaf(s, w[i], acc[r][i]);
        }
        #pragma unroll
        for (int i = 0; i < 4; i++) w[i] = wn[i];
    }
    // per-row LN stats
    #pragma unroll
    for (int r = 0; r < IMG_ROWS; r++) {
        float s = 0.f, q = 0.f;
        #pragma unroll
        for (int i = 0; i < 4; i++) { s += acc[r][i]; q += acc[r][i] * acc[r][i]; }
        const unsigned m = 0xffffffffu;
        #pragma unroll
        for (int o = 16; o; o >>= 1) {
            s += __shfl_down_sync(m, s, o);
            q += __shfl_down_sync(m, q, o);
        }
        if (lid == 0) { red[r][wid][0] = s; red[r][wid][1] = q; }
    }
    __syncthreads();
    #pragma unroll
    for (int r = 0; r < IMG_ROWS; r++) {
        float s = 0.f, q = 0.f;
        #pragma unroll
        for (int wi = 0; wi < 8; wi++) { s += red[r][wi][0]; q += red[r][wi][1]; }
        float mean = s * (1.f / NHID);
        float var = q * (1.f / NHID) - mean * mean;
        float rstd = rsqrtf(var + LN_EPS);
        #pragma unroll
        for (int i = 0; i < 4; i++) {
            int c = tid + i * 256;
            float v = elu1((acc[r][i] - mean) * rstd * gamma[c] + beta[c]);
            split_store(g_xh_hi, g_xh_lo, (size_t)(b0 + r) * 2048 + c, v);
        }
    }
}

__global__ void k_gru(const float* __restrict__ gamma, const float* __restrict__ beta,
                      float* __restrict__ out, int t) {
    __shared__ float red[16];
    const int b = blockIdx.x, tid = threadIdx.x;
    const float* p = g_parts + (long)b * 3072;
    float v[12];
    float s = 0.f, q = 0.f;
    #pragma unroll
    for (int i = 0; i < 12; i++) {
        v[i] = p[tid + i * 256];
        s += v[i]; q += v[i] * v[i];
    }
    blk_red2(s, q, red);
    float mean = s * (1.f / 3072.f);
    float var = q * (1.f / 3072.f) - mean * mean;
    float rstd = rsqrtf(var + LN_EPS);
    float* outr = out + ((long)b * NT + t) * NOUT;
    #pragma unroll
    for (int i = 0; i < 4; i++) {
        int j = tid + i * 256;
        float r = (v[i]     - mean) * rstd * gamma[j]        + beta[j];
        float c = (v[i + 4] - mean) * rstd * gamma[1024 + j] + beta[1024 + j];
        float u = (v[i + 8] - mean) * rstd * gamma[2048 + j] + beta[2048 + j];
        r = sigm(r);
        c = tanhf(r * c);
        u = sigm(u - 1.f);
        float dold = g_xh[(long)b * 2048 + 1024 + j];
        float d = u * c + (1.f - u) * dold;
        g_xh[(long)b * 2048 + 1024 + j] = d;
        outr[128 + j] = d;
        split_store(g_xh_hi, g_xh_lo, (size_t)b * 2048 + 1024 + j, d);
    }
}

__global__ void k_lnelu(const float* __restrict__ gamma, const float* __restrict__ beta) {
    __shared__ float red[16];
    const int b = blockIdx.x, tid = threadIdx.x;
    const float* h = g_h + (long)b * NHID;
    float v[4];
    float s = 0.f, q = 0.f;
    #pragma unroll
    for (int i = 0; i < 4; i++) {
        v[i] = h[tid + i * 256];
        s += v[i]; q += v[i] * v[i];
    }
    blk_red2(s, q, red);
    float mean = s * (1.f / NHID);
    float var = q * (1.f / NHID) - mean * mean;
    float rstd = rsqrtf(var + LN_EPS);
    #pragma unroll
    for (int i = 0; i < 4; i++) {
        int c = tid + i * 256;
        float val = elu1((v[i] - mean) * rstd * gamma[c] + beta[c]);
        split_store(g_h_hi, g_h_lo, (size_t)b * NHID + c, val);
    }
}

// reduce split-K partials + bias, then stoch/std epilogue
__global__ void k_stats(const float* __restrict__ bias, float* __restrict__ out, int t) {
    int idx = blockIdx.x * blockDim.x + threadIdx.x;
    if (idx >= NB * NSTOCH) return;
    int b = idx / NSTOCH, s = idx % NSTOCH;
    float mean = bias[s], sr = bias[64 + s];
    #pragma unroll
    for (int sp = 0; sp < E2_SPLITS; sp++) {
        const float* P = g_stats_part + (size_t)sp * (NB * 128) + (size_t)b * 128;
        mean += P[s];
        sr += P[64 + s];
    }
    float std = softplus1(sr) + 0.1f;
    g_stoch[idx] = mean;
    float* outr = out + ((long)b * NT + t) * NOUT;
    outr[s] = mean;
    outr[64 + s] = std;
}

// ---------------- HMMA bf16x3 GEMM ----------------
// Computes chunks [z*cps, min((z+1)*cps, 3*K/64)) of the phase-concatenated K loop.
// For split-K (gridDim.z > 1): bias == nullptr, C offset by z * part_stride.
__global__ void __launch_bounds__(256, 1) gemm_hmma(
    const __nv_bfloat16* __restrict__ Ahi, const __nv_bfloat16* __restrict__ Alo,
    int lda, int K,
    const __nv_bfloat16* __restrict__ Bhi, const __nv_bfloat16* __restrict__ Blo,
    const float* __restrict__ bias, float* __restrict__ C, int ldc,
    int cps, long part_stride) {
    extern __shared__ char smem[];
    const int tid = threadIdx.x, lid = tid & 31, wid = tid >> 5;
    const int wm = wid & 1, wn = wid >> 1;          // 2 x 4 warp grid
    const int bx = blockIdx.x, by = blockIdx.y, bz = blockIdx.z;
    const uint32_t sbase = smem_u32(smem);

    const int kpp = K >> 6;
    const int NCg = 3 * kpp;
    const int c0 = bz * cps;
    const int NC = (c0 + cps < NCg ? cps : NCg - c0);
    C += (long)bz * part_stride;

    const int lr = lid & 7, sub = lid >> 3;
    const uint32_t a_off = (uint32_t)((wm * 64 + (sub & 1) * 8 + lr) * ROWB
                                      + ((sub >> 1) * 8) * 2);
    const uint32_t b_off0 = (uint32_t)((wn * 32 + (sub >> 1) * 8 + lr) * ROWB
                                       + ((sub & 1) * 8) * 2);
    const uint32_t b_off1 = b_off0 + 16 * ROWB;

    float acc[4][4][4];
    #pragma unroll
    for (int i = 0; i < 4; i++)
        #pragma unroll
        for (int j = 0; j < 4; j++)
            #pragma unroll
            for (int k = 0; k < 4; k++) acc[i][j][k] = 0.f;

    auto issue = [&](int ccl, int stg) {
        int cc = c0 + ccl;
        int p = cc / kpp, j = cc - p * kpp, k0 = j << 6;
        const __nv_bfloat16* As = (p == 1) ? Alo : Ahi;
        const __nv_bfloat16* Bs = (p == 2) ? Blo : Bhi;
        uint32_t sa = sbase + stg * STAGE_BYTES;
        uint32_t sb = sa + 128 * ROWB;
        #pragma unroll
        for (int i = 0; i < 4; i++) {
            int c = tid + i * 256, r = c >> 3, sg = c & 7;
            cp16(sa + r * ROWB + sg * 16, As + (size_t)(by * BMT + r) * lda + k0 + sg * 8);
            cp16(sb + r * ROWB + sg * 16, Bs + (size_t)(bx * BNT + r) * K + k0 + sg * 8);
        }
    };

    issue(0, 0); CP_COMMIT();
    if (NC > 1) issue(1, 1);
    CP_COMMIT();

    for (int cc = 0; cc < NC; cc++) {
        CP_WAIT1();
        __syncthreads();
        int cp = cc + 2;
        if (cp < NC) issue(cp, cp % NSTG);
        CP_COMMIT();

        uint32_t sa = sbase + (cc % NSTG) * STAGE_BYTES;
        uint32_t sb = sa + 128 * ROWB;
        #pragma unroll
        for (int ks = 0; ks < 4; ks++) {
            uint32_t afr[4][4], bfr[2][4];
            ldsm4(bfr[0], sb + b_off0 + ks * 32);
            ldsm4(bfr[1], sb + b_off1 + ks * 32);
            #pragma unroll
            for (int mi = 0; mi < 4; mi++)
                ldsm4(afr[mi], sa + a_off + mi * (16 * ROWB) + ks * 32);
            #pragma unroll
            for (int mi = 0; mi < 4; mi++)
                #pragma unroll
                for (int ni = 0; ni < 4; ni++)
                    mma16816(acc[mi][ni], afr[mi], &bfr[ni >> 1][(ni & 1) * 2]);
        }
    }

    const int row_base = by * BMT + wm * 64 + (lid >> 2);
    const int col_base = bx * BNT + wn * 32 + (lid & 3) * 2;
    #pragma unroll
    for (int ni = 0; ni < 4; ni++) {
        int cg = col_base + ni * 8;
        float b0 = bias ? bias[cg] : 0.f;
        float b1 = bias ? bias[cg + 1] : 0.f;
        #pragma unroll
        for (int mi = 0; mi < 4; mi++) {
            int r = row_base + mi * 16;
            float2 v0 = { acc[mi][ni][0] + b0, acc[mi][ni][1] + b1 };
            float2 v1 = { acc[mi][ni][2] + b0, acc[mi][ni][3] + b1 };
            *(float2*)(C + (size_t)r * ldc + cg) = v0;
            *(float2*)(C + (size_t)(r + 8) * ldc + cg) = v1;
        }
    }
}

// ---------------- launcher ----------------
extern "C" void kernel_launch(void* const* d_in, const int* in_sizes, int n_in,
                              void* d_out, int out_size) {
    const float* action = (const float*)d_in[0];
    const float* W_img  = (const float*)d_in[1];
    const float* b_img  = (const float*)d_in[2];
    const float* gi     = (const float*)d_in[3];
    const float* bei    = (const float*)d_in[4];
    const float* W_gru  = (const float*)d_in[5];
    const float* b_gru  = (const float*)d_in[6];
    const float* gg     = (const float*)d_in[7];
    const float* beg    = (const float*)d_in[8];
    const float* W_e1   = (const float*)d_in[9];
    const float* b_e1   = (const float*)d_in[10];
    const float* ge1    = (const float*)d_in[11];
    const float* bee1   = (const float*)d_in[12];
    const float* W_e2   = (const float*)d_in[13];
    const float* b_e2   = (const float*)d_in[14];
    float* out = (float*)d_out;

    void *p_parts, *p_h, *p_sp, *p_xh_hi, *p_xh_lo, *p_h_hi, *p_h_lo;
    void *p_wg_hi, *p_wg_lo, *p_we1_hi, *p_we1_lo, *p_we2_hi, *p_we2_lo;
    cudaGetSymbolAddress(&p_parts, g_parts);
    cudaGetSymbolAddress(&p_h, g_h);
    cudaGetSymbolAddress(&p_sp, g_stats_part);
    cudaGetSymbolAddress(&p_xh_hi, g_xh_hi);
    cudaGetSymbolAddress(&p_xh_lo, g_xh_lo);
    cudaGetSymbolAddress(&p_h_hi, g_h_hi);
    cudaGetSymbolAddress(&p_h_lo, g_h_lo);
    cudaGetSymbolAddress(&p_wg_hi, g_wg_hi);
    cudaGetSymbolAddress(&p_wg_lo, g_wg_lo);
    cudaGetSymbolAddress(&p_we1_hi, g_we1_hi);
    cudaGetSymbolAddress(&p_we1_lo, g_we1_lo);
    cudaGetSymbolAddress(&p_we2_hi, g_we2_hi);
    cudaGetSymbolAddress(&p_we2_lo, g_we2_lo);

    cudaFuncSetAttribute(gemm_hmma, cudaFuncAttributeMaxDynamicSharedMemorySize, SMEM_SZ);

    k_zero<<<512, 256>>>();
    wtrans<<<dim3(3072 / 32, 2048 / 32), dim3(32, 8)>>>(
        W_gru, (__nv_bfloat16*)p_wg_hi, (__nv_bfloat16*)p_wg_lo, 2048, 3072);
    wtrans<<<dim3(1024 / 32, 1024 / 32), dim3(32, 8)>>>(
        W_e1, (__nv_bfloat16*)p_we1_hi, (__nv_bfloat16*)p_we1_lo, 1024, 1024);
    wtrans<<<dim3(128 / 32, 1024 / 32), dim3(32, 8)>>>(
        W_e2, (__nv_bfloat16*)p_we2_hi, (__nv_bfloat16*)p_we2_lo, 1024, 128);

    const dim3 g_gru(3072 / BNT, 2048 / BMT, 1);       // 24 x 16
    const dim3 g_e1(1024 / BNT, 2048 / BMT, 1);        //  8 x 16
    const dim3 g_e2(128 / BNT, 2048 / BMT, E2_SPLITS); //  1 x 16 x 8
    const int e2_cps = (3 * (1024 / 64)) / E2_SPLITS;  // 48/8 = 6

    for (int t = 0; t < NT; t++) {
        k_img<<<NB / IMG_ROWS, 256>>>(action, W_img, b_img, gi, bei, t);
        gemm_hmma<<<g_gru, 256, SMEM_SZ>>>(
            (__nv_bfloat16*)p_xh_hi, (__nv_bfloat16*)p_xh_lo, 2048, 2048,
            (__nv_bfloat16*)p_wg_hi, (__nv_bfloat16*)p_wg_lo,
            b_gru, (float*)p_parts, 3072, 3 * (2048 / 64), 0);
        k_gru<<<NB, 256>>>(gg, beg, out, t);
        gemm_hmma<<<g_e1, 256, SMEM_SZ>>>(
            (__nv_bfloat16*)p_xh_hi + 1024, (__nv_bfloat16*)p_xh_lo + 1024, 2048, 1024,
            (__nv_bfloat16*)p_we1_hi, (__nv_bfloat16*)p_we1_lo,
            b_e1, (float*)p_h, 1024, 3 * (1024 / 64), 0);
        k_lnelu<<<NB, 256>>>(ge1, bee1);
        gemm_hmma<<<g_e2, 256, SMEM_SZ>>>(
            (__nv_bfloat16*)p_h_hi, (__nv_bfloat16*)p_h_lo, 1024, 1024,
            (__nv_bfloat16*)p_we2_hi, (__nv_bfloat16*)p_we2_lo,
            nullptr, (float*)p_sp, 128, e2_cps, (long)NB * 128);
        k_stats<<<(NB * NSTOCH + 255) / 256, 256>>>(b_e2, out, t);
    }
    (void)in_sizes; (void)n_in; (void)out_size;
}

// round 9
// speedup vs baseline: 2.3715x; 1.1171x over previous
#include <cuda_runtime.h>
#include <cuda_bf16.h>
#include <math.h>
#include <stdint.h>

#define NB 2048
#define NT 30
#define NACT 6
#define NSTOCH 64
#define NDETER 1024
#define NHID 1024
#define NOUT 1152
#define LN_EPS 1e-5f

// GEMM tiling
#define BMT 128
#define BNT 128
#define ROWB 144                       // 64 bf16 = 128B + 16B pad
#define STAGE_BYTES (128 * ROWB * 2)   // A tile + B tile = 36864
#define NSTG 2
#define SMEM_SZ (NSTG * STAGE_BYTES)   // 73728 -> 2 CTAs/SM

#define E2_SPLITS 8

// ---------------- persistent buffers ----------------
__device__ float g_xh[NB * 2048];      // fp32 [x | deter] (deter half used by k_gru)
__device__ float g_parts[NB * 3072];
__device__ float g_h[NB * NHID];
__device__ float g_stats_part[E2_SPLITS * NB * 128];
__device__ float g_stoch[NB * NSTOCH];

__device__ __align__(16) __nv_bfloat16 g_xh_hi[NB * 2048];
__device__ __align__(16) __nv_bfloat16 g_xh_lo[NB * 2048];
__device__ __align__(16) __nv_bfloat16 g_h_hi[NB * NHID];
__device__ __align__(16) __nv_bfloat16 g_h_lo[NB * NHID];
__device__ __align__(16) __nv_bfloat16 g_wg_hi[3072 * 2048];
__device__ __align__(16) __nv_bfloat16 g_wg_lo[3072 * 2048];
__device__ __align__(16) __nv_bfloat16 g_we1_hi[1024 * 1024];
__device__ __align__(16) __nv_bfloat16 g_we1_lo[1024 * 1024];
__device__ __align__(16) __nv_bfloat16 g_we2_hi[128 * 1024];
__device__ __align__(16) __nv_bfloat16 g_we2_lo[128 * 1024];

// ---------------- helpers ----------------
__device__ __forceinline__ float elu1(float x) { return x > 0.f ? x : (expf(x) - 1.f); }
__device__ __forceinline__ float sigm(float x) { return 1.f / (1.f + expf(-x)); }
__device__ __forceinline__ float softplus1(float x) {
    return x > 0.f ? x + log1pf(expf(-x)) : log1pf(expf(x));
}
__device__ __forceinline__ void split_store(__nv_bfloat16* hi, __nv_bfloat16* lo,
                                            size_t idx, float v) {
    __nv_bfloat16 h = __float2bfloat16(v);
    hi[idx] = h;
    lo[idx] = __float2bfloat16(v - __bfloat162float(h));
}
__device__ __forceinline__ uint32_t smem_u32(const void* p) {
    uint32_t a;
    asm("{ .reg .u64 t; cvta.to.shared.u64 t, %1; cvt.u32.u64 %0, t; }" : "=r"(a) : "l"(p));
    return a;
}
__device__ __forceinline__ void cp16(uint32_t s, const void* g) {
    asm volatile("cp.async.cg.shared.global [%0], [%1], 16;" :: "r"(s), "l"(g));
}
__device__ __forceinline__ void ldsm4(uint32_t* r, uint32_t addr) {
    asm volatile("ldmatrix.sync.aligned.m8n8.x4.shared.b16 {%0,%1,%2,%3}, [%4];"
        : "=r"(r[0]), "=r"(r[1]), "=r"(r[2]), "=r"(r[3]) : "r"(addr));
}
__device__ __forceinline__ void mma16816(float* d, const uint32_t* a, const uint32_t* b) {
    asm volatile("mma.sync.aligned.m16n8k16.row.col.f32.bf16.bf16.f32 "
        "{%0,%1,%2,%3}, {%4,%5,%6,%7}, {%8,%9}, {%0,%1,%2,%3};"
        : "+f"(d[0]), "+f"(d[1]), "+f"(d[2]), "+f"(d[3])
        : "r"(a[0]), "r"(a[1]), "r"(a[2]), "r"(a[3]), "r"(b[0]), "r"(b[1]));
}
#define CP_COMMIT() asm volatile("cp.async.commit_group;" ::: "memory")
#define CP_WAIT0()  asm volatile("cp.async.wait_group 0;" ::: "memory")

// ---------------- reductions ----------------
__device__ __forceinline__ void blk_red2(float& s, float& q, float* sh) {
    const unsigned m = 0xffffffffu;
    #pragma unroll
    for (int o = 16; o; o >>= 1) {
        s += __shfl_down_sync(m, s, o);
        q += __shfl_down_sync(m, q, o);
    }
    int w = threadIdx.x >> 5, l = threadIdx.x & 31;
    int nw = blockDim.x >> 5;
    if (l == 0) { sh[2 * w] = s; sh[2 * w + 1] = q; }
    __syncthreads();
    if (threadIdx.x == 0) {
        float ts = 0.f, tq = 0.f;
        for (int i = 0; i < nw; i++) { ts += sh[2 * i]; tq += sh[2 * i + 1]; }
        sh[0] = ts; sh[1] = tq;
    }
    __syncthreads();
    s = sh[0]; q = sh[1];
    __syncthreads();
}

// ---------------- init / weight transpose+split ----------------
__global__ void k_zero() {
    long i0 = blockIdx.x * (long)blockDim.x + threadIdx.x;
    long stride = (long)gridDim.x * blockDim.x;
    for (long i = i0; i < (long)NB * 2048; i += stride) g_xh[i] = 0.f;
    for (long i = i0; i < (long)NB * NSTOCH; i += stride) g_stoch[i] = 0.f;
    unsigned short* hi = (unsigned short*)g_xh_hi;
    unsigned short* lo = (unsigned short*)g_xh_lo;
    for (long i = i0; i < (long)NB * 2048; i += stride) { hi[i] = 0; lo[i] = 0; }
}

__global__ void wtrans(const float* __restrict__ W, __nv_bfloat16* __restrict__ hi,
                       __nv_bfloat16* __restrict__ lo, int K, int N) {
    __shared__ float s[32][33];
    int k0 = blockIdx.y * 32, n0 = blockIdx.x * 32;
    int tx = threadIdx.x, ty = threadIdx.y;
    #pragma unroll
    for (int j = 0; j < 4; j++)
        s[ty + j * 8][tx] = W[(size_t)(k0 + ty + j * 8) * N + n0 + tx];
    __syncthreads();
    #pragma unroll
    for (int j = 0; j < 4; j++) {
        int n = n0 + ty + j * 8, k = k0 + tx;
        split_store(hi, lo, (size_t)n * K + k, s[tx][ty + j * 8]);
    }
}

// ---------------- fused pointwise kernels ----------------
#define IMG_ROWS 16
__global__ void __launch_bounds__(256) k_img(
    const float* __restrict__ action, const float* __restrict__ W,
    const float* __restrict__ bias, const float* __restrict__ gamma,
    const float* __restrict__ beta, int t) {
    __shared__ float sbuf[IMG_ROWS][72];
    __shared__ float red[IMG_ROWS][8][2];
    const int b0 = blockIdx.x * IMG_ROWS, tid = threadIdx.x;
    const int wid = tid >> 5, lid = tid & 31;

    for (int idx = tid; idx < IMG_ROWS * 70; idx += 256) {
        int r = idx / 70, k = idx % 70;
        float v = (k < NSTOCH) ? g_stoch[(b0 + r) * NSTOCH + k]
                               : action[((long)(b0 + r) * NT + t) * NACT + (k - NSTOCH)];
        sbuf[r][k] = v;
    }
    __syncthreads();

    float acc[IMG_ROWS][4];
    {
        float bz[4];
        #pragma unroll
        for (int i = 0; i < 4; i++) bz[i] = bias[tid + i * 256];
        #pragma unroll
        for (int r = 0; r < IMG_ROWS; r++)
            #pragma unroll
            for (int i = 0; i < 4; i++) acc[r][i] = bz[i];
    }
    float w[4], wn[4];
    #pragma unroll
    for (int i = 0; i < 4; i++) w[i] = W[tid + i * 256];
    for (int k = 0; k < 70; k++) {
        if (k + 1 < 70) {
            const float* Wk = W + (long)(k + 1) * NHID;
            #pragma unroll
            for (int i = 0; i < 4; i++) wn[i] = Wk[tid + i * 256];
        }
        #pragma unroll
        for (int r = 0; r < IMG_ROWS; r++) {
            float s = sbuf[r][k];
            #pragma unroll
            for (int i = 0; i < 4; i++) acc[r][i] = fmaf(s, w[i], acc[r][i]);
        }
        #pragma unroll
        for (int i = 0; i < 4; i++) w[i] = wn[i];
    }
    #pragma unroll
    for (int r = 0; r < IMG_ROWS; r++) {
        float s = 0.f, q = 0.f;
        #pragma unroll
        for (int i = 0; i < 4; i++) { s += acc[r][i]; q += acc[r][i] * acc[r][i]; }
        const unsigned m = 0xffffffffu;
        #pragma unroll
        for (int o = 16; o; o >>= 1) {
            s += __shfl_down_sync(m, s, o);
            q += __shfl_down_sync(m, q, o);
        }
        if (lid == 0) { red[r][wid][0] = s; red[r][wid][1] = q; }
    }
    __syncthreads();
    #pragma unroll
    for (int r = 0; r < IMG_ROWS; r++) {
        float s = 0.f, q = 0.f;
        #pragma unroll
        for (int wi = 0; wi < 8; wi++) { s += red[r][wi][0]; q += red[r][wi][1]; }
        float mean = s * (1.f / NHID);
        float var = q * (1.f / NHID) - mean * mean;
        float rstd = rsqrtf(var + LN_EPS);
        #pragma unroll
        for (int i = 0; i < 4; i++) {
            int c = tid + i * 256;
            float v = elu1((acc[r][i] - mean) * rstd * gamma[c] + beta[c]);
            split_store(g_xh_hi, g_xh_lo, (size_t)(b0 + r) * 2048 + c, v);
        }
    }
}

__global__ void k_gru(const float* __restrict__ gamma, const float* __restrict__ beta,
                      float* __restrict__ out, int t) {
    __shared__ float red[16];
    const int b = blockIdx.x, tid = threadIdx.x;
    const float* p = g_parts + (long)b * 3072;
    float v[12];
    float s = 0.f, q = 0.f;
    #pragma unroll
    for (int i = 0; i < 12; i++) {
        v[i] = p[tid + i * 256];
        s += v[i]; q += v[i] * v[i];
    }
    blk_red2(s, q, red);
    float mean = s * (1.f / 3072.f);
    float var = q * (1.f / 3072.f) - mean * mean;
    float rstd = rsqrtf(var + LN_EPS);
    float* outr = out + ((long)b * NT + t) * NOUT;
    #pragma unroll
    for (int i = 0; i < 4; i++) {
        int j = tid + i * 256;
        float r = (v[i]     - mean) * rstd * gamma[j]        + beta[j];
        float c = (v[i + 4] - mean) * rstd * gamma[1024 + j] + beta[1024 + j];
        float u = (v[i + 8] - mean) * rstd * gamma[2048 + j] + beta[2048 + j];
        r = sigm(r);
        c = tanhf(r * c);
        u = sigm(u - 1.f);
        float dold = g_xh[(long)b * 2048 + 1024 + j];
        float d = u * c + (1.f - u) * dold;
        g_xh[(long)b * 2048 + 1024 + j] = d;
        outr[128 + j] = d;
        split_store(g_xh_hi, g_xh_lo, (size_t)b * 2048 + 1024 + j, d);
    }
}

__global__ void k_lnelu(const float* __restrict__ gamma, const float* __restrict__ beta) {
    __shared__ float red[16];
    const int b = blockIdx.x, tid = threadIdx.x;
    const float* h = g_h + (long)b * NHID;
    float v[4];
    float s = 0.f, q = 0.f;
    #pragma unroll
    for (int i = 0; i < 4; i++) {
        v[i] = h[tid + i * 256];
        s += v[i]; q += v[i] * v[i];
    }
    blk_red2(s, q, red);
    float mean = s * (1.f / NHID);
    float var = q * (1.f / NHID) - mean * mean;
    float rstd = rsqrtf(var + LN_EPS);
    #pragma unroll
    for (int i = 0; i < 4; i++) {
        int c = tid + i * 256;
        float val = elu1((v[i] - mean) * rstd * gamma[c] + beta[c]);
        split_store(g_h_hi, g_h_lo, (size_t)b * NHID + c, val);
    }
}

__global__ void k_stats(const float* __restrict__ bias, float* __restrict__ out, int t) {
    int idx = blockIdx.x * blockDim.x + threadIdx.x;
    if (idx >= NB * NSTOCH) return;
    int b = idx / NSTOCH, s = idx % NSTOCH;
    float mean = bias[s], sr = bias[64 + s];
    #pragma unroll
    for (int sp = 0; sp < E2_SPLITS; sp++) {
        const float* P = g_stats_part + (size_t)sp * (NB * 128) + (size_t)b * 128;
        mean += P[s];
        sr += P[64 + s];
    }
    float std = softplus1(sr) + 0.1f;
    g_stoch[idx] = mean;
    float* outr = out + ((long)b * NT + t) * NOUT;
    outr[s] = mean;
    outr[64 + s] = std;
}

// ---------------- HMMA bf16x3 GEMM (2-stage, 2 CTAs/SM) ----------------
__global__ void __launch_bounds__(256, 2) gemm_hmma(
    const __nv_bfloat16* __restrict__ Ahi, const __nv_bfloat16* __restrict__ Alo,
    int lda, int K,
    const __nv_bfloat16* __restrict__ Bhi, const __nv_bfloat16* __restrict__ Blo,
    const float* __restrict__ bias, float* __restrict__ C, int ldc,
    int cps, long part_stride) {
    extern __shared__ char smem[];
    const int tid = threadIdx.x, lid = tid & 31, wid = tid >> 5;
    const int wm = wid & 1, wn = wid >> 1;          // 2 x 4 warp grid
    const int bx = blockIdx.x, by = blockIdx.y, bz = blockIdx.z;
    const uint32_t sbase = smem_u32(smem);

    const int kpp = K >> 6;
    const int NCg = 3 * kpp;
    const int c0 = bz * cps;
    const int NC = (c0 + cps < NCg ? cps : NCg - c0);
    C += (long)bz * part_stride;

    const int lr = lid & 7, sub = lid >> 3;
    const uint32_t a_off = (uint32_t)((wm * 64 + (sub & 1) * 8 + lr) * ROWB
                                      + ((sub >> 1) * 8) * 2);
    const uint32_t b_off0 = (uint32_t)((wn * 32 + (sub >> 1) * 8 + lr) * ROWB
                                       + ((sub & 1) * 8) * 2);
    const uint32_t b_off1 = b_off0 + 16 * ROWB;

    float acc[4][4][4];
    #pragma unroll
    for (int i = 0; i < 4; i++)
        #pragma unroll
        for (int j = 0; j < 4; j++)
            #pragma unroll
            for (int k = 0; k < 4; k++) acc[i][j][k] = 0.f;

    auto issue = [&](int ccl, int stg) {
        int cc = c0 + ccl;
        int p = cc / kpp, j = cc - p * kpp, k0 = j << 6;
        const __nv_bfloat16* As = (p == 1) ? Alo : Ahi;
        const __nv_bfloat16* Bs = (p == 2) ? Blo : Bhi;
        uint32_t sa = sbase + stg * STAGE_BYTES;
        uint32_t sb = sa + 128 * ROWB;
        #pragma unroll
        for (int i = 0; i < 4; i++) {
            int c = tid + i * 256, r = c >> 3, sg = c & 7;
            cp16(sa + r * ROWB + sg * 16, As + (size_t)(by * BMT + r) * lda + k0 + sg * 8);
            cp16(sb + r * ROWB + sg * 16, Bs + (size_t)(bx * BNT + r) * K + k0 + sg * 8);
        }
    };

    issue(0, 0); CP_COMMIT();

    for (int cc = 0; cc < NC; cc++) {
        CP_WAIT0();                 // chunk cc resident
        __syncthreads();            // visible to all; guards stage reuse (compute cc-1 done)
        if (cc + 1 < NC) { issue(cc + 1, (cc + 1) & 1); CP_COMMIT(); }

        uint32_t sa = sbase + (cc & 1) * STAGE_BYTES;
        uint32_t sb = sa + 128 * ROWB;
        #pragma unroll
        for (int ks = 0; ks < 4; ks++) {
            uint32_t afr[4][4], bfr[2][4];
            ldsm4(bfr[0], sb + b_off0 + ks * 32);
            ldsm4(bfr[1], sb + b_off1 + ks * 32);
            #pragma unroll
            for (int mi = 0; mi < 4; mi++)
                ldsm4(afr[mi], sa + a_off + mi * (16 * ROWB) + ks * 32);
            #pragma unroll
            for (int mi = 0; mi < 4; mi++)
                #pragma unroll
                for (int ni = 0; ni < 4; ni++)
                    mma16816(acc[mi][ni], afr[mi], &bfr[ni >> 1][(ni & 1) * 2]);
        }
        __syncthreads();            // all warps done with stage (cc&1) before overwrite
    }

    const int row_base = by * BMT + wm * 64 + (lid >> 2);
    const int col_base = bx * BNT + wn * 32 + (lid & 3) * 2;
    #pragma unroll
    for (int ni = 0; ni < 4; ni++) {
        int cg = col_base + ni * 8;
        float b0 = bias ? bias[cg] : 0.f;
        float b1 = bias ? bias[cg + 1] : 0.f;
        #pragma unroll
        for (int mi = 0; mi < 4; mi++) {
            int r = row_base + mi * 16;
            float2 v0 = { acc[mi][ni][0] + b0, acc[mi][ni][1] + b1 };
            float2 v1 = { acc[mi][ni][2] + b0, acc[mi][ni][3] + b1 };
            *(float2*)(C + (size_t)r * ldc + cg) = v0;
            *(float2*)(C + (size_t)(r + 8) * ldc + cg) = v1;
        }
    }
}

// ---------------- launcher ----------------
extern "C" void kernel_launch(void* const* d_in, const int* in_sizes, int n_in,
                              void* d_out, int out_size) {
    const float* action = (const float*)d_in[0];
    const float* W_img  = (const float*)d_in[1];
    const float* b_img  = (const float*)d_in[2];
    const float* gi     = (const float*)d_in[3];
    const float* bei    = (const float*)d_in[4];
    const float* W_gru  = (const float*)d_in[5];
    const float* b_gru  = (const float*)d_in[6];
    const float* gg     = (const float*)d_in[7];
    const float* beg    = (const float*)d_in[8];
    const float* W_e1   = (const float*)d_in[9];
    const float* b_e1   = (const float*)d_in[10];
    const float* ge1    = (const float*)d_in[11];
    const float* bee1   = (const float*)d_in[12];
    const float* W_e2   = (const float*)d_in[13];
    const float* b_e2   = (const float*)d_in[14];
    float* out = (float*)d_out;

    void *p_parts, *p_h, *p_sp, *p_xh_hi, *p_xh_lo, *p_h_hi, *p_h_lo;
    void *p_wg_hi, *p_wg_lo, *p_we1_hi, *p_we1_lo, *p_we2_hi, *p_we2_lo;
    cudaGetSymbolAddress(&p_parts, g_parts);
    cudaGetSymbolAddress(&p_h, g_h);
    cudaGetSymbolAddress(&p_sp, g_stats_part);
    cudaGetSymbolAddress(&p_xh_hi, g_xh_hi);
    cudaGetSymbolAddress(&p_xh_lo, g_xh_lo);
    cudaGetSymbolAddress(&p_h_hi, g_h_hi);
    cudaGetSymbolAddress(&p_h_lo, g_h_lo);
    cudaGetSymbolAddress(&p_wg_hi, g_wg_hi);
    cudaGetSymbolAddress(&p_wg_lo, g_wg_lo);
    cudaGetSymbolAddress(&p_we1_hi, g_we1_hi);
    cudaGetSymbolAddress(&p_we1_lo, g_we1_lo);
    cudaGetSymbolAddress(&p_we2_hi, g_we2_hi);
    cudaGetSymbolAddress(&p_we2_lo, g_we2_lo);

    cudaFuncSetAttribute(gemm_hmma, cudaFuncAttributeMaxDynamicSharedMemorySize, SMEM_SZ);

    k_zero<<<512, 256>>>();
    wtrans<<<dim3(3072 / 32, 2048 / 32), dim3(32, 8)>>>(
        W_gru, (__nv_bfloat16*)p_wg_hi, (__nv_bfloat16*)p_wg_lo, 2048, 3072);
    wtrans<<<dim3(1024 / 32, 1024 / 32), dim3(32, 8)>>>(
        W_e1, (__nv_bfloat16*)p_we1_hi, (__nv_bfloat16*)p_we1_lo, 1024, 1024);
    wtrans<<<dim3(128 / 32, 1024 / 32), dim3(32, 8)>>>(
        W_e2, (__nv_bfloat16*)p_we2_hi, (__nv_bfloat16*)p_we2_lo, 1024, 128);

    const dim3 g_gru(3072 / BNT, 2048 / BMT, 1);       // 24 x 16
    const dim3 g_e1(1024 / BNT, 2048 / BMT, 1);        //  8 x 16
    const dim3 g_e2(128 / BNT, 2048 / BMT, E2_SPLITS); //  1 x 16 x 8
    const int e2_cps = (3 * (1024 / 64)) / E2_SPLITS;  // 6

    for (int t = 0; t < NT; t++) {
        k_img<<<NB / IMG_ROWS, 256>>>(action, W_img, b_img, gi, bei, t);
        gemm_hmma<<<g_gru, 256, SMEM_SZ>>>(
            (__nv_bfloat16*)p_xh_hi, (__nv_bfloat16*)p_xh_lo, 2048, 2048,
            (__nv_bfloat16*)p_wg_hi, (__nv_bfloat16*)p_wg_lo,
            b_gru, (float*)p_parts, 3072, 3 * (2048 / 64), 0);
        k_gru<<<NB, 256>>>(gg, beg, out, t);
        gemm_hmma<<<g_e1, 256, SMEM_SZ>>>(
            (__nv_bfloat16*)p_xh_hi + 1024, (__nv_bfloat16*)p_xh_lo + 1024, 2048, 1024,
            (__nv_bfloat16*)p_we1_hi, (__nv_bfloat16*)p_we1_lo,
            b_e1, (float*)p_h, 1024, 3 * (1024 / 64), 0);
        k_lnelu<<<NB, 256>>>(ge1, bee1);
        gemm_hmma<<<g_e2, 256, SMEM_SZ>>>(
            (__nv_bfloat16*)p_h_hi, (__nv_bfloat16*)p_h_lo, 1024, 1024,
            (__nv_bfloat16*)p_we2_hi, (__nv_bfloat16*)p_we2_lo,
            nullptr, (float*)p_sp, 128, e2_cps, (long)NB * 128);
        k_stats<<<(NB * NSTOCH + 255) / 256, 256>>>(b_e2, out, t);
    }
    (void)in_sizes; (void)n_in; (void)out_size;
}

// round 11
// speedup vs baseline: 3.2975x; 1.3905x over previous
#include <cuda_runtime.h>
#include <cuda_fp16.h>
#include <math.h>
#include <stdint.h>

#define NB 2048
#define NT 30
#define NACT 6
#define NSTOCH 64
#define NDETER 1024
#define NHID 1024
#define NOUT 1152
#define LN_EPS 1e-5f

// GEMM tiling
#define BMT 128
#define BNT 128
#define ROWB 144                       // 64 fp16 = 128B + 16B pad
#define STAGE_BYTES (128 * ROWB * 2)   // A tile + B tile = 36864
#define SMEM_SZ (2 * STAGE_BYTES)      // 73728 -> 2 CTAs/SM

#define GRU_SPLITS 2
#define E1_SPLITS 2
#define E2_SPLITS 8

// ---------------- persistent buffers ----------------
__device__ float g_deter[NB * NDETER];                    // fp32 recurrent state
__device__ float g_parts_part[GRU_SPLITS * NB * 3072];    // GRU split-K partials
__device__ float g_h_part[E1_SPLITS * NB * NHID];         // e1 split-K partials
__device__ float g_stats_part[E2_SPLITS * NB * 128];
__device__ float g_stoch[NB * NSTOCH];

__device__ __align__(16) __half g_xh_f16[NB * 2048];      // A: [x | deter] fp16
__device__ __align__(16) __half g_h_f16[NB * NHID];       // A of e2
__device__ __align__(16) __half g_wg_hi[3072 * 2048];     // W_gru^T [N,K] hi/lo
__device__ __align__(16) __half g_wg_lo[3072 * 2048];
__device__ __align__(16) __half g_we1_hi[1024 * 1024];
__device__ __align__(16) __half g_we1_lo[1024 * 1024];
__device__ __align__(16) __half g_we2_hi[128 * 1024];
__device__ __align__(16) __half g_we2_lo[128 * 1024];

// ---------------- helpers ----------------
__device__ __forceinline__ float elu1(float x) { return x > 0.f ? x : (expf(x) - 1.f); }
__device__ __forceinline__ float sigm(float x) { return 1.f / (1.f + expf(-x)); }
__device__ __forceinline__ float softplus1(float x) {
    return x > 0.f ? x + log1pf(expf(-x)) : log1pf(expf(x));
}
__device__ __forceinline__ void wsplit(__half* hi, __half* lo, size_t idx, float v) {
    __half h = __float2half(v);
    hi[idx] = h;
    lo[idx] = __float2half(v - __half2float(h));
}
__device__ __forceinline__ uint32_t smem_u32(const void* p) {
    uint32_t a;
    asm("{ .reg .u64 t; cvta.to.shared.u64 t, %1; cvt.u32.u64 %0, t; }" : "=r"(a) : "l"(p));
    return a;
}
__device__ __forceinline__ void cp16(uint32_t s, const void* g) {
    asm volatile("cp.async.cg.shared.global [%0], [%1], 16;" :: "r"(s), "l"(g));
}
__device__ __forceinline__ void ldsm4(uint32_t* r, uint32_t addr) {
    asm volatile("ldmatrix.sync.aligned.m8n8.x4.shared.b16 {%0,%1,%2,%3}, [%4];"
        : "=r"(r[0]), "=r"(r[1]), "=r"(r[2]), "=r"(r[3]) : "r"(addr));
}
__device__ __forceinline__ void mma16816(float* d, const uint32_t* a, const uint32_t* b) {
    asm volatile("mma.sync.aligned.m16n8k16.row.col.f32.f16.f16.f32 "
        "{%0,%1,%2,%3}, {%4,%5,%6,%7}, {%8,%9}, {%0,%1,%2,%3};"
        : "+f"(d[0]), "+f"(d[1]), "+f"(d[2]), "+f"(d[3])
        : "r"(a[0]), "r"(a[1]), "r"(a[2]), "r"(a[3]), "r"(b[0]), "r"(b[1]));
}
#define CP_COMMIT() asm volatile("cp.async.commit_group;" ::: "memory")
#define CP_WAIT0()  asm volatile("cp.async.wait_group 0;" ::: "memory")

// ---------------- reductions ----------------
__device__ __forceinline__ void blk_red2(float& s, float& q, float* sh) {
    const unsigned m = 0xffffffffu;
    #pragma unroll
    for (int o = 16; o; o >>= 1) {
        s += __shfl_down_sync(m, s, o);
        q += __shfl_down_sync(m, q, o);
    }
    int w = threadIdx.x >> 5, l = threadIdx.x & 31;
    int nw = blockDim.x >> 5;
    if (l == 0) { sh[2 * w] = s; sh[2 * w + 1] = q; }
    __syncthreads();
    if (threadIdx.x == 0) {
        float ts = 0.f, tq = 0.f;
        for (int i = 0; i < nw; i++) { ts += sh[2 * i]; tq += sh[2 * i + 1]; }
        sh[0] = ts; sh[1] = tq;
    }
    __syncthreads();
    s = sh[0]; q = sh[1];
    __syncthreads();
}

// ---------------- init / weight transpose+split ----------------
__global__ void k_zero() {
    long i0 = blockIdx.x * (long)blockDim.x + threadIdx.x;
    long stride = (long)gridDim.x * blockDim.x;
    for (long i = i0; i < (long)NB * NDETER; i += stride) g_deter[i] = 0.f;
    for (long i = i0; i < (long)NB * NSTOCH; i += stride) g_stoch[i] = 0.f;
    unsigned short* a = (unsigned short*)g_xh_f16;
    for (long i = i0; i < (long)NB * 2048; i += stride) a[i] = 0;
}

// W [K,N] fp32 -> Wt hi/lo [N,K] fp16
__global__ void wtrans(const float* __restrict__ W, __half* __restrict__ hi,
                       __half* __restrict__ lo, int K, int N) {
    __shared__ float s[32][33];
    int k0 = blockIdx.y * 32, n0 = blockIdx.x * 32;
    int tx = threadIdx.x, ty = threadIdx.y;
    #pragma unroll
    for (int j = 0; j < 4; j++)
        s[ty + j * 8][tx] = W[(size_t)(k0 + ty + j * 8) * N + n0 + tx];
    __syncthreads();
    #pragma unroll
    for (int j = 0; j < 4; j++) {
        int n = n0 + ty + j * 8, k = k0 + tx;
        wsplit(hi, lo, (size_t)n * K + k, s[tx][ty + j * 8]);
    }
}

// ---------------- fused pointwise kernels ----------------
#define IMG_ROWS 16
__global__ void __launch_bounds__(256) k_img(
    const float* __restrict__ action, const float* __restrict__ W,
    const float* __restrict__ bias, const float* __restrict__ gamma,
    const float* __restrict__ beta, int t) {
    __shared__ float sbuf[IMG_ROWS][72];
    __shared__ float red[IMG_ROWS][8][2];
    const int b0 = blockIdx.x * IMG_ROWS, tid = threadIdx.x;
    const int wid = tid >> 5, lid = tid & 31;

    for (int idx = tid; idx < IMG_ROWS * 70; idx += 256) {
        int r = idx / 70, k = idx % 70;
        float v = (k < NSTOCH) ? g_stoch[(b0 + r) * NSTOCH + k]
                               : action[((long)(b0 + r) * NT + t) * NACT + (k - NSTOCH)];
        sbuf[r][k] = v;
    }
    __syncthreads();

    float acc[IMG_ROWS][4];
    {
        float bz[4];
        #pragma unroll
        for (int i = 0; i < 4; i++) bz[i] = bias[tid + i * 256];
        #pragma unroll
        for (int r = 0; r < IMG_ROWS; r++)
            #pragma unroll
            for (int i = 0; i < 4; i++) acc[r][i] = bz[i];
    }
    float w[4], wn[4];
    #pragma unroll
    for (int i = 0; i < 4; i++) w[i] = W[tid + i * 256];
    for (int k = 0; k < 70; k++) {
        if (k + 1 < 70) {
            const float* Wk = W + (long)(k + 1) * NHID;
            #pragma unroll
            for (int i = 0; i < 4; i++) wn[i] = Wk[tid + i * 256];
        }
        #pragma unroll
        for (int r = 0; r < IMG_ROWS; r++) {
            float s = sbuf[r][k];
            #pragma unroll
            for (int i = 0; i < 4; i++) acc[r][i] = fmaf(s, w[i], acc[r][i]);
        }
        #pragma unroll
        for (int i = 0; i < 4; i++) w[i] = wn[i];
    }
    #pragma unroll
    for (int r = 0; r < IMG_ROWS; r++) {
        float s = 0.f, q = 0.f;
        #pragma unroll
        for (int i = 0; i < 4; i++) { s += acc[r][i]; q += acc[r][i] * acc[r][i]; }
        const unsigned m = 0xffffffffu;
        #pragma unroll
        for (int o = 16; o; o >>= 1) {
            s += __shfl_down_sync(m, s, o);
            q += __shfl_down_sync(m, q, o);
        }
        if (lid == 0) { red[r][wid][0] = s; red[r][wid][1] = q; }
    }
    __syncthreads();
    #pragma unroll
    for (int r = 0; r < IMG_ROWS; r++) {
        float s = 0.f, q = 0.f;
        #pragma unroll
        for (int wi = 0; wi < 8; wi++) { s += red[r][wi][0]; q += red[r][wi][1]; }
        float mean = s * (1.f / NHID);
        float var = q * (1.f / NHID) - mean * mean;
        float rstd = rsqrtf(var + LN_EPS);
        #pragma unroll
        for (int i = 0; i < 4; i++) {
            int c = tid + i * 256;
            float v = elu1((acc[r][i] - mean) * rstd * gamma[c] + beta[c]);
            g_xh_f16[(size_t)(b0 + r) * 2048 + c] = __float2half(v);
        }
    }
}

// sum GRU split-K partials + bias -> LN -> gates -> new deter
__global__ void k_gru(const float* __restrict__ bias, const float* __restrict__ gamma,
                      const float* __restrict__ beta, float* __restrict__ out, int t) {
    __shared__ float red[16];
    const int b = blockIdx.x, tid = threadIdx.x;
    const float* p0 = g_parts_part + (long)b * 3072;
    const float* p1 = g_parts_part + (long)NB * 3072 + (long)b * 3072;
    float v[12];
    float s = 0.f, q = 0.f;
    #pragma unroll
    for (int i = 0; i < 12; i++) {
        int j = tid + i * 256;
        v[i] = p0[j] + p1[j] + bias[j];
        s += v[i]; q += v[i] * v[i];
    }
    blk_red2(s, q, red);
    float mean = s * (1.f / 3072.f);
    float var = q * (1.f / 3072.f) - mean * mean;
    float rstd = rsqrtf(var + LN_EPS);
    float* outr = out + ((long)b * NT + t) * NOUT;
    #pragma unroll
    for (int i = 0; i < 4; i++) {
        int j = tid + i * 256;
        float r = (v[i]     - mean) * rstd * gamma[j]        + beta[j];
        float c = (v[i + 4] - mean) * rstd * gamma[1024 + j] + beta[1024 + j];
        float u = (v[i + 8] - mean) * rstd * gamma[2048 + j] + beta[2048 + j];
        r = sigm(r);
        c = tanhf(r * c);
        u = sigm(u - 1.f);
        float dold = g_deter[(long)b * NDETER + j];
        float d = u * c + (1.f - u) * dold;
        g_deter[(long)b * NDETER + j] = d;
        outr[128 + j] = d;
        g_xh_f16[(size_t)b * 2048 + 1024 + j] = __float2half(d);
    }
}

// sum e1 split-K partials + bias -> LN -> ELU -> fp16 A of e2
__global__ void k_lnelu(const float* __restrict__ bias, const float* __restrict__ gamma,
                        const float* __restrict__ beta) {
    __shared__ float red[16];
    const int b = blockIdx.x, tid = threadIdx.x;
    const float* p0 = g_h_part + (long)b * NHID;
    const float* p1 = g_h_part + (long)NB * NHID + (long)b * NHID;
    float v[4];
    float s = 0.f, q = 0.f;
    #pragma unroll
    for (int i = 0; i < 4; i++) {
        int c = tid + i * 256;
        v[i] = p0[c] + p1[c] + bias[c];
        s += v[i]; q += v[i] * v[i];
    }
    blk_red2(s, q, red);
    float mean = s * (1.f / NHID);
    float var = q * (1.f / NHID) - mean * mean;
    float rstd = rsqrtf(var + LN_EPS);
    #pragma unroll
    for (int i = 0; i < 4; i++) {
        int c = tid + i * 256;
        float val = elu1((v[i] - mean) * rstd * gamma[c] + beta[c]);
        g_h_f16[(size_t)b * NHID + c] = __float2half(val);
    }
}

__global__ void k_stats(const float* __restrict__ bias, float* __restrict__ out, int t) {
    int idx = blockIdx.x * blockDim.x + threadIdx.x;
    if (idx >= NB * NSTOCH) return;
    int b = idx / NSTOCH, s = idx % NSTOCH;
    float mean = bias[s], sr = bias[64 + s];
    #pragma unroll
    for (int sp = 0; sp < E2_SPLITS; sp++) {
        const float* P = g_stats_part + (size_t)sp * (NB * 128) + (size_t)b * 128;
        mean += P[s];
        sr += P[64 + s];
    }
    float std = softplus1(sr) + 0.1f;
    g_stoch[idx] = mean;
    float* outr = out + ((long)b * NT + t) * NOUT;
    outr[s] = mean;
    outr[64 + s] = std;
}

// ---------------- HMMA fp16x2 GEMM (2-stage, 2 CTAs/SM, split-K) ----------------
// C_part[bz] = sum over chunks [bz*cps, ...) of A[M,K] @ (Bh|Bl)[N,K]^T
// chunk cc: phase p = cc/kpp selects Bhi (p=0) or Blo (p=1); A identical across phases.
__global__ void __launch_bounds__(256, 2) gemm_hmma(
    const __half* __restrict__ A, int lda, int K,
    const __half* __restrict__ Bhi, const __half* __restrict__ Blo,
    float* __restrict__ C, int ldc, int cps, long part_stride) {
    extern __shared__ char smem[];
    const int tid = threadIdx.x, lid = tid & 31, wid = tid >> 5;
    const int wm = wid & 1, wn = wid >> 1;
    const int bx = blockIdx.x, by = blockIdx.y, bz = blockIdx.z;
    const uint32_t sbase = smem_u32(smem);

    const int kpp = K >> 6;
    const int NCg = 2 * kpp;
    const int c0 = bz * cps;
    const int NC = (c0 + cps < NCg ? cps : NCg - c0);
    C += (long)bz * part_stride;

    const int lr = lid & 7, sub = lid >> 3;
    const uint32_t a_off = (uint32_t)((wm * 64 + (sub & 1) * 8 + lr) * ROWB
                                      + ((sub >> 1) * 8) * 2);
    const uint32_t b_off0 = (uint32_t)((wn * 32 + (sub >> 1) * 8 + lr) * ROWB
                                       + ((sub & 1) * 8) * 2);
    const uint32_t b_off1 = b_off0 + 16 * ROWB;

    float acc[4][4][4];
    #pragma unroll
    for (int i = 0; i < 4; i++)
        #pragma unroll
        for (int j = 0; j < 4; j++)
            #pragma unroll
            for (int k = 0; k < 4; k++) acc[i][j][k] = 0.f;

    auto issue = [&](int ccl, int stg) {
        int cc = c0 + ccl;
        int p = cc / kpp, j = cc - p * kpp, k0 = j << 6;
        const __half* Bs = p ? Blo : Bhi;
        uint32_t sa = sbase + stg * STAGE_BYTES;
        uint32_t sb = sa + 128 * ROWB;
        #pragma unroll
        for (int i = 0; i < 4; i++) {
            int c = tid + i * 256, r = c >> 3, sg = c & 7;
            cp16(sa + r * ROWB + sg * 16, A + (size_t)(by * BMT + r) * lda + k0 + sg * 8);
            cp16(sb + r * ROWB + sg * 16, Bs + (size_t)(bx * BNT + r) * K + k0 + sg * 8);
        }
    };

    issue(0, 0); CP_COMMIT();

    for (int cc = 0; cc < NC; cc++) {
        CP_WAIT0();
        __syncthreads();
        if (cc + 1 < NC) { issue(cc + 1, (cc + 1) & 1); CP_COMMIT(); }

        uint32_t sa = sbase + (cc & 1) * STAGE_BYTES;
        uint32_t sb = sa + 128 * ROWB;
        #pragma unroll
        for (int ks = 0; ks < 4; ks++) {
            uint32_t afr[4][4], bfr[2][4];
            ldsm4(bfr[0], sb + b_off0 + ks * 32);
            ldsm4(bfr[1], sb + b_off1 + ks * 32);
            #pragma unroll
            for (int mi = 0; mi < 4; mi++)
                ldsm4(afr[mi], sa + a_off + mi * (16 * ROWB) + ks * 32);
            #pragma unroll
            for (int mi = 0; mi < 4; mi++)
                #pragma unroll
                for (int ni = 0; ni < 4; ni++)
                    mma16816(acc[mi][ni], afr[mi], &bfr[ni >> 1][(ni & 1) * 2]);
        }
        __syncthreads();
    }

    const int row_base = by * BMT + wm * 64 + (lid >> 2);
    const int col_base = bx * BNT + wn * 32 + (lid & 3) * 2;
    #pragma unroll
    for (int ni = 0; ni < 4; ni++) {
        int cg = col_base + ni * 8;
        #pragma unroll
        for (int mi = 0; mi < 4; mi++) {
            int r = row_base + mi * 16;
            float2 v0 = { acc[mi][ni][0], acc[mi][ni][1] };
            float2 v1 = { acc[mi][ni][2], acc[mi][ni][3] };
            *(float2*)(C + (size_t)r * ldc + cg) = v0;
            *(float2*)(C + (size_t)(r + 8) * ldc + cg) = v1;
        }
    }
}

// ---------------- launcher ----------------
extern "C" void kernel_launch(void* const* d_in, const int* in_sizes, int n_in,
                              void* d_out, int out_size) {
    const float* action = (const float*)d_in[0];
    const float* W_img  = (const float*)d_in[1];
    const float* b_img  = (const float*)d_in[2];
    const float* gi     = (const float*)d_in[3];
    const float* bei    = (const float*)d_in[4];
    const float* W_gru  = (const float*)d_in[5];
    const float* b_gru  = (const float*)d_in[6];
    const float* gg     = (const float*)d_in[7];
    const float* beg    = (const float*)d_in[8];
    const float* W_e1   = (const float*)d_in[9];
    const float* b_e1   = (const float*)d_in[10];
    const float* ge1    = (const float*)d_in[11];
    const float* bee1   = (const float*)d_in[12];
    const float* W_e2   = (const float*)d_in[13];
    const float* b_e2   = (const float*)d_in[14];
    float* out = (float*)d_out;

    void *p_pp, *p_hp, *p_sp, *p_a, *p_hf;
    void *p_wg_hi, *p_wg_lo, *p_we1_hi, *p_we1_lo, *p_we2_hi, *p_we2_lo;
    cudaGetSymbolAddress(&p_pp, g_parts_part);
    cudaGetSymbolAddress(&p_hp, g_h_part);
    cudaGetSymbolAddress(&p_sp, g_stats_part);
    cudaGetSymbolAddress(&p_a, g_xh_f16);
    cudaGetSymbolAddress(&p_hf, g_h_f16);
    cudaGetSymbolAddress(&p_wg_hi, g_wg_hi);
    cudaGetSymbolAddress(&p_wg_lo, g_wg_lo);
    cudaGetSymbolAddress(&p_we1_hi, g_we1_hi);
    cudaGetSymbolAddress(&p_we1_lo, g_we1_lo);
    cudaGetSymbolAddress(&p_we2_hi, g_we2_hi);
    cudaGetSymbolAddress(&p_we2_lo, g_we2_lo);

    cudaFuncSetAttribute(gemm_hmma, cudaFuncAttributeMaxDynamicSharedMemorySize, SMEM_SZ);

    k_zero<<<512, 256>>>();
    wtrans<<<dim3(3072 / 32, 2048 / 32), dim3(32, 8)>>>(
        W_gru, (__half*)p_wg_hi, (__half*)p_wg_lo, 2048, 3072);
    wtrans<<<dim3(1024 / 32, 1024 / 32), dim3(32, 8)>>>(
        W_e1, (__half*)p_we1_hi, (__half*)p_we1_lo, 1024, 1024);
    wtrans<<<dim3(128 / 32, 1024 / 32), dim3(32, 8)>>>(
        W_e2, (__half*)p_we2_hi, (__half*)p_we2_lo, 1024, 128);

    const dim3 g_gru(3072 / BNT, 2048 / BMT, GRU_SPLITS);  // 24 x 16 x 2 = 768
    const dim3 g_e1(1024 / BNT, 2048 / BMT, E1_SPLITS);    //  8 x 16 x 2 = 256
    const dim3 g_e2(128 / BNT, 2048 / BMT, E2_SPLITS);     //  1 x 16 x 8 = 128
    const int gru_cps = (2 * (2048 / 64)) / GRU_SPLITS;    // 32
    const int e1_cps  = (2 * (1024 / 64)) / E1_SPLITS;     // 16
    const int e2_cps  = (2 * (1024 / 64)) / E2_SPLITS;     // 4

    for (int t = 0; t < NT; t++) {
        k_img<<<NB / IMG_ROWS, 256>>>(action, W_img, b_img, gi, bei, t);
        gemm_hmma<<<g_gru, 256, SMEM_SZ>>>(
            (__half*)p_a, 2048, 2048,
            (__half*)p_wg_hi, (__half*)p_wg_lo,
            (float*)p_pp, 3072, gru_cps, (long)NB * 3072);
        k_gru<<<NB, 256>>>(b_gru, gg, beg, out, t);
        gemm_hmma<<<g_e1, 256, SMEM_SZ>>>(
            (__half*)p_a + 1024, 2048, 1024,
            (__half*)p_we1_hi, (__half*)p_we1_lo,
            (float*)p_hp, 1024, e1_cps, (long)NB * 1024);
        k_lnelu<<<NB, 256>>>(b_e1, ge1, bee1);
        gemm_hmma<<<g_e2, 256, SMEM_SZ>>>(
            (__half*)p_hf, 1024, 1024,
            (__half*)p_we2_hi, (__half*)p_we2_lo,
            (float*)p_sp, 128, e2_cps, (long)NB * 128);
        k_stats<<<(NB * NSTOCH + 255) / 256, 256>>>(b_e2, out, t);
    }
    (void)in_sizes; (void)n_in; (void)out_size;
}

// round 15
// speedup vs baseline: 3.7866x; 1.1483x over previous
#include <cuda_runtime.h>
#include <cuda_fp16.h>
#include <math.h>
#include <stdint.h>

#define NB 2048
#define NT 30
#define NACT 6
#define NSTOCH 64
#define NDETER 1024
#define NHID 1024
#define NOUT 1152
#define LN_EPS 1e-5f

// GEMM tiling
#define BMT 128
#define BNT 128
#define ROWB 144                   // 64 fp16 = 128B + 16B pad
#define TILEB (128 * ROWB)         // 18432 per tile
#define STG_BYTES (3 * TILEB)      // A + Bh + Bl = 55296
#define SMEM_SZ (2 * STG_BYTES)    // 110592 -> 2 CTAs/SM (221KB of 228KB)

#define GRU_SPLITS 2
#define E1_SPLITS 2
#define E2_SPLITS 8

// ---------------- persistent buffers ----------------
__device__ float g_deter[NB * NDETER];
__device__ float g_parts_part[GRU_SPLITS * NB * 3072];
__device__ float g_h_part[E1_SPLITS * NB * NHID];
__device__ float g_stats_part[E2_SPLITS * NB * 128];

__device__ __align__(16) __half g_xh_f16[NB * 2048];
__device__ __align__(16) __half g_h_f16[NB * NHID];
__device__ __align__(16) __half g_wg_hi[3072 * 2048];
__device__ __align__(16) __half g_wg_lo[3072 * 2048];
__device__ __align__(16) __half g_we1_hi[1024 * 1024];
__device__ __align__(16) __half g_we1_lo[1024 * 1024];
__device__ __align__(16) __half g_we2_hi[128 * 1024];
__device__ __align__(16) __half g_we2_lo[128 * 1024];

// ---------------- helpers ----------------
__device__ __forceinline__ float elu1(float x) { return x > 0.f ? x : (expf(x) - 1.f); }
__device__ __forceinline__ float sigm(float x) { return 1.f / (1.f + expf(-x)); }
__device__ __forceinline__ float softplus1(float x) {
    return x > 0.f ? x + log1pf(expf(-x)) : log1pf(expf(x));
}
__device__ __forceinline__ void wsplit(__half* hi, __half* lo, size_t idx, float v) {
    __half h = __float2half(v);
    hi[idx] = h;
    lo[idx] = __float2half(v - __half2float(h));
}
__device__ __forceinline__ uint32_t smem_u32(const void* p) {
    uint32_t a;
    asm("{ .reg .u64 t; cvta.to.shared.u64 t, %1; cvt.u32.u64 %0, t; }" : "=r"(a) : "l"(p));
    return a;
}
__device__ __forceinline__ void cp16(uint32_t s, const void* g) {
    asm volatile("cp.async.cg.shared.global [%0], [%1], 16;" :: "r"(s), "l"(g));
}
__device__ __forceinline__ void ldsm4(uint32_t* r, uint32_t addr) {
    asm volatile("ldmatrix.sync.aligned.m8n8.x4.shared.b16 {%0,%1,%2,%3}, [%4];"
        : "=r"(r[0]), "=r"(r[1]), "=r"(r[2]), "=r"(r[3]) : "r"(addr));
}
__device__ __forceinline__ void mma16816(float* d, const uint32_t* a, const uint32_t* b) {
    asm volatile("mma.sync.aligned.m16n8k16.row.col.f32.f16.f16.f32 "
        "{%0,%1,%2,%3}, {%4,%5,%6,%7}, {%8,%9}, {%0,%1,%2,%3};"
        : "+f"(d[0]), "+f"(d[1]), "+f"(d[2]), "+f"(d[3])
        : "r"(a[0]), "r"(a[1]), "r"(a[2]), "r"(a[3]), "r"(b[0]), "r"(b[1]));
}
#define CP_COMMIT() asm volatile("cp.async.commit_group;" ::: "memory")
#define CP_WAIT0()  asm volatile("cp.async.wait_group 0;" ::: "memory")

// ---------------- reductions ----------------
__device__ __forceinline__ void blk_red2(float& s, float& q, float* sh) {
    const unsigned m = 0xffffffffu;
    #pragma unroll
    for (int o = 16; o; o >>= 1) {
        s += __shfl_down_sync(m, s, o);
        q += __shfl_down_sync(m, q, o);
    }
    int w = threadIdx.x >> 5, l = threadIdx.x & 31;
    int nw = blockDim.x >> 5;
    if (l == 0) { sh[2 * w] = s; sh[2 * w + 1] = q; }
    __syncthreads();
    if (threadIdx.x == 0) {
        float ts = 0.f, tq = 0.f;
        for (int i = 0; i < nw; i++) { ts += sh[2 * i]; tq += sh[2 * i + 1]; }
        sh[0] = ts; sh[1] = tq;
    }
    __syncthreads();
    s = sh[0]; q = sh[1];
    __syncthreads();
}

// ---------------- init / weight transpose+split ----------------
__global__ void k_zero() {
    long i0 = blockIdx.x * (long)blockDim.x + threadIdx.x;
    long stride = (long)gridDim.x * blockDim.x;
    for (long i = i0; i < (long)NB * NDETER; i += stride) g_deter[i] = 0.f;
    unsigned short* a = (unsigned short*)g_xh_f16;
    for (long i = i0; i < (long)NB * 2048; i += stride) a[i] = 0;
}

__global__ void wtrans(const float* __restrict__ W, __half* __restrict__ hi,
                       __half* __restrict__ lo, int K, int N) {
    __shared__ float s[32][33];
    int k0 = blockIdx.y * 32, n0 = blockIdx.x * 32;
    int tx = threadIdx.x, ty = threadIdx.y;
    #pragma unroll
    for (int j = 0; j < 4; j++)
        s[ty + j * 8][tx] = W[(size_t)(k0 + ty + j * 8) * N + n0 + tx];
    __syncthreads();
    #pragma unroll
    for (int j = 0; j < 4; j++) {
        int n = n0 + ty + j * 8, k = k0 + tx;
        wsplit(hi, lo, (size_t)n * K + k, s[tx][ty + j * 8]);
    }
}

// ---------------- fused pointwise kernels ----------------
// k_img(t): if t>0, reduce e2 split-K partials of step t-1 into stoch/std
// (writes out[t-1] slice), then img linear + LN + ELU -> fp16 A cols 0..1023.
#define IMG_ROWS 16
__global__ void __launch_bounds__(256) k_img(
    const float* __restrict__ action, const float* __restrict__ W,
    const float* __restrict__ bias, const float* __restrict__ gamma,
    const float* __restrict__ beta, const float* __restrict__ be2,
    float* __restrict__ out, int t) {
    __shared__ float sbuf[IMG_ROWS][72];
    __shared__ float red[IMG_ROWS][8][2];
    const int b0 = blockIdx.x * IMG_ROWS, tid = threadIdx.x;
    const int wid = tid >> 5, lid = tid & 31;

    if (t > 0) {
        for (int it = tid; it < IMG_ROWS * NSTOCH; it += 256) {
            int r = it >> 6, s = it & 63;
            int b = b0 + r;
            float mean = be2[s], sr = be2[64 + s];
            #pragma unroll
            for (int sp = 0; sp < E2_SPLITS; sp++) {
                const float* P = g_stats_part + (size_t)sp * (NB * 128) + (size_t)b * 128;
                mean += P[s];
                sr += P[64 + s];
            }
            float std = softplus1(sr) + 0.1f;
            sbuf[r][s] = mean;
            float* outr = out + ((long)b * NT + (t - 1)) * NOUT;
            outr[s] = mean;
            outr[64 + s] = std;
        }
    } else {
        for (int it = tid; it < IMG_ROWS * NSTOCH; it += 256)
            sbuf[it >> 6][it & 63] = 0.f;
    }
    for (int it = tid; it < IMG_ROWS * NACT; it += 256) {
        int r = it / NACT, k = it % NACT;
        sbuf[r][NSTOCH + k] = action[((long)(b0 + r) * NT + t) * NACT + k];
    }
    __syncthreads();

    float acc[IMG_ROWS][4];
    {
        float bz[4];
        #pragma unroll
        for (int i = 0; i < 4; i++) bz[i] = bias[tid + i * 256];
        #pragma unroll
        for (int r = 0; r < IMG_ROWS; r++)
            #pragma unroll
            for (int i = 0; i < 4; i++) acc[r][i] = bz[i];
    }
    float w[4], wn[4];
    #pragma unroll
    for (int i = 0; i < 4; i++) w[i] = W[tid + i * 256];
    for (int k = 0; k < 70; k++) {
        if (k + 1 < 70) {
            const float* Wk = W + (long)(k + 1) * NHID;
            #pragma unroll
            for (int i = 0; i < 4; i++) wn[i] = Wk[tid + i * 256];
        }
        #pragma unroll
        for (int r = 0; r < IMG_ROWS; r++) {
            float s = sbuf[r][k];
            #pragma unroll
            for (int i = 0; i < 4; i++) acc[r][i] = fmaf(s, w[i], acc[r][i]);
        }
        #pragma unroll
        for (int i = 0; i < 4; i++) w[i] = wn[i];
    }
    #pragma unroll
    for (int r = 0; r < IMG_ROWS; r++) {
        float s = 0.f, q = 0.f;
        #pragma unroll
        for (int i = 0; i < 4; i++) { s += acc[r][i]; q += acc[r][i] * acc[r][i]; }
        const unsigned m = 0xffffffffu;
        #pragma unroll
        for (int o = 16; o; o >>= 1) {
            s += __shfl_down_sync(m, s, o);
            q += __shfl_down_sync(m, q, o);
        }
        if (lid == 0) { red[r][wid][0] = s; red[r][wid][1] = q; }
    }
    __syncthreads();
    #pragma unroll
    for (int r = 0; r < IMG_ROWS; r++) {
        float s = 0.f, q = 0.f;
        #pragma unroll
        for (int wi = 0; wi < 8; wi++) { s += red[r][wi][0]; q += red[r][wi][1]; }
        float mean = s * (1.f / NHID);
        float var = q * (1.f / NHID) - mean * mean;
        float rstd = rsqrtf(var + LN_EPS);
        #pragma unroll
        for (int i = 0; i < 4; i++) {
            int c = tid + i * 256;
            float v = elu1((acc[r][i] - mean) * rstd * gamma[c] + beta[c]);
            g_xh_f16[(size_t)(b0 + r) * 2048 + c] = __float2half(v);
        }
    }
}

__global__ void k_gru(const float* __restrict__ bias, const float* __restrict__ gamma,
                      const float* __restrict__ beta, float* __restrict__ out, int t) {
    __shared__ float red[16];
    const int b = blockIdx.x, tid = threadIdx.x;
    const float* p0 = g_parts_part + (long)b * 3072;
    const float* p1 = g_parts_part + (long)NB * 3072 + (long)b * 3072;
    float v[12];
    float s = 0.f, q = 0.f;
    #pragma unroll
    for (int i = 0; i < 12; i++) {
        int j = tid + i * 256;
        v[i] = p0[j] + p1[j] + bias[j];
        s += v[i]; q += v[i] * v[i];
    }
    blk_red2(s, q, red);
    float mean = s * (1.f / 3072.f);
    float var = q * (1.f / 3072.f) - mean * mean;
    float rstd = rsqrtf(var + LN_EPS);
    float* outr = out + ((long)b * NT + t) * NOUT;
    #pragma unroll
    for (int i = 0; i < 4; i++) {
        int j = tid + i * 256;
        float r = (v[i]     - mean) * rstd * gamma[j]        + beta[j];
        float c = (v[i + 4] - mean) * rstd * gamma[1024 + j] + beta[1024 + j];
        float u = (v[i + 8] - mean) * rstd * gamma[2048 + j] + beta[2048 + j];
        r = sigm(r);
        c = tanhf(r * c);
        u = sigm(u - 1.f);
        float dold = g_deter[(long)b * NDETER + j];
        float d = u * c + (1.f - u) * dold;
        g_deter[(long)b * NDETER + j] = d;
        outr[128 + j] = d;
        g_xh_f16[(size_t)b * 2048 + 1024 + j] = __float2half(d);
    }
}

__global__ void k_lnelu(const float* __restrict__ bias, const float* __restrict__ gamma,
                        const float* __restrict__ beta) {
    __shared__ float red[16];
    const int b = blockIdx.x, tid = threadIdx.x;
    const float* p0 = g_h_part + (long)b * NHID;
    const float* p1 = g_h_part + (long)NB * NHID + (long)b * NHID;
    float v[4];
    float s = 0.f, q = 0.f;
    #pragma unroll
    for (int i = 0; i < 4; i++) {
        int c = tid + i * 256;
        v[i] = p0[c] + p1[c] + bias[c];
        s += v[i]; q += v[i] * v[i];
    }
    blk_red2(s, q, red);
    float mean = s * (1.f / NHID);
    float var = q * (1.f / NHID) - mean * mean;
    float rstd = rsqrtf(var + LN_EPS);
    #pragma unroll
    for (int i = 0; i < 4; i++) {
        int c = tid + i * 256;
        float val = elu1((v[i] - mean) * rstd * gamma[c] + beta[c]);
        g_h_f16[(size_t)b * NHID + c] = __float2half(val);
    }
}

// final-step stats epilogue (runs once, after the time loop, for t = NT-1)
__global__ void k_stats(const float* __restrict__ bias, float* __restrict__ out, int t) {
    int idx = blockIdx.x * blockDim.x + threadIdx.x;
    if (idx >= NB * NSTOCH) return;
    int b = idx / NSTOCH, s = idx % NSTOCH;
    float mean = bias[s], sr = bias[64 + s];
    #pragma unroll
    for (int sp = 0; sp < E2_SPLITS; sp++) {
        const float* P = g_stats_part + (size_t)sp * (NB * 128) + (size_t)b * 128;
        mean += P[s];
        sr += P[64 + s];
    }
    float std = softplus1(sr) + 0.1f;
    float* outr = out + ((long)b * NT + t) * NOUT;
    outr[s] = mean;
    outr[64 + s] = std;
}

// ---------------- HMMA fp16x2 GEMM, A reused across both B phases ----------------
__global__ void __launch_bounds__(256, 2) gemm_hmma(
    const __half* __restrict__ A, int lda, int K,
    const __half* __restrict__ Bhi, const __half* __restrict__ Blo,
    float* __restrict__ C, int ldc, int cps, long part_stride) {
    extern __shared__ char smem[];
    const int tid = threadIdx.x, lid = tid & 31, wid = tid >> 5;
    const int wm = wid & 1, wn = wid >> 1;
    const int bx = blockIdx.x, by = blockIdx.y, bz = blockIdx.z;
    const uint32_t sbase = smem_u32(smem);

    const int kpp = K >> 6;
    const int c0 = bz * cps;
    const int NC = (c0 + cps < kpp ? cps : kpp - c0);
    C += (long)bz * part_stride;

    const int lr = lid & 7, sub = lid >> 3;
    const uint32_t a_off = (uint32_t)((wm * 64 + (sub & 1) * 8 + lr) * ROWB
                                      + ((sub >> 1) * 8) * 2);
    const uint32_t b_off0 = (uint32_t)((wn * 32 + (sub >> 1) * 8 + lr) * ROWB
                                       + ((sub & 1) * 8) * 2);
    const uint32_t b_off1 = b_off0 + 16 * ROWB;

    float acc[4][4][4];
    #pragma unroll
    for (int i = 0; i < 4; i++)
        #pragma unroll
        for (int j = 0; j < 4; j++)
            #pragma unroll
            for (int k = 0; k < 4; k++) acc[i][j][k] = 0.f;

    auto issue = [&](int ccl, int stg) {
        int k0 = (c0 + ccl) << 6;
        uint32_t sa = sbase + stg * STG_BYTES;
        #pragma unroll
        for (int i = 0; i < 4; i++) {
            int c = tid + i * 256, r = c >> 3, sg = c & 7;
            uint32_t d = r * ROWB + sg * 16;
            cp16(sa + d, A + (size_t)(by * BMT + r) * lda + k0 + sg * 8);
            cp16(sa + TILEB + d, Bhi + (size_t)(bx * BNT + r) * K + k0 + sg * 8);
            cp16(sa + 2 * TILEB + d, Blo + (size_t)(bx * BNT + r) * K + k0 + sg * 8);
        }
    };

    issue(0, 0); CP_COMMIT();

    for (int cc = 0; cc < NC; cc++) {
        CP_WAIT0();
        __syncthreads();
        if (cc + 1 < NC) { issue(cc + 1, (cc + 1) & 1); CP_COMMIT(); }

        uint32_t sa = sbase + (cc & 1) * STG_BYTES;
        #pragma unroll
        for (int ks = 0; ks < 4; ks++) {
            uint32_t afr[4][4];
            #pragma unroll
            for (int mi = 0; mi < 4; mi++)
                ldsm4(afr[mi], sa + a_off + mi * (16 * ROWB) + ks * 32);
            {
                uint32_t bfr[2][4];
                ldsm4(bfr[0], sa + TILEB + b_off0 + ks * 32);
                ldsm4(bfr[1], sa + TILEB + b_off1 + ks * 32);
                #pragma unroll
                for (int mi = 0; mi < 4; mi++)
                    #pragma unroll
                    for (int ni = 0; ni < 4; ni++)
                        mma16816(acc[mi][ni], afr[mi], &bfr[ni >> 1][(ni & 1) * 2]);
            }
            {
                uint32_t bfr[2][4];
                ldsm4(bfr[0], sa + 2 * TILEB + b_off0 + ks * 32);
                ldsm4(bfr[1], sa + 2 * TILEB + b_off1 + ks * 32);
                #pragma unroll
                for (int mi = 0; mi < 4; mi++)
                    #pragma unroll
                    for (int ni = 0; ni < 4; ni++)
                        mma16816(acc[mi][ni], afr[mi], &bfr[ni >> 1][(ni & 1) * 2]);
            }
        }
        __syncthreads();
    }

    const int row_base = by * BMT + wm * 64 + (lid >> 2);
    const int col_base = bx * BNT + wn * 32 + (lid & 3) * 2;
    #pragma unroll
    for (int ni = 0; ni < 4; ni++) {
        int cg = col_base + ni * 8;
        #pragma unroll
        for (int mi = 0; mi < 4; mi++) {
            int r = row_base + mi * 16;
            float2 v0 = { acc[mi][ni][0], acc[mi][ni][1] };
            float2 v1 = { acc[mi][ni][2], acc[mi][ni][3] };
            *(float2*)(C + (size_t)r * ldc + cg) = v0;
            *(float2*)(C + (size_t)(r + 8) * ldc + cg) = v1;
        }
    }
}

// ---------------- launcher ----------------
extern "C" void kernel_launch(void* const* d_in, const int* in_sizes, int n_in,
                              void* d_out, int out_size) {
    const float* action = (const float*)d_in[0];
    const float* W_img  = (const float*)d_in[1];
    const float* b_img  = (const float*)d_in[2];
    const float* gi     = (const float*)d_in[3];
    const float* bei    = (const float*)d_in[4];
    const float* W_gru  = (const float*)d_in[5];
    const float* b_gru  = (const float*)d_in[6];
    const float* gg     = (const float*)d_in[7];
    const float* beg    = (const float*)d_in[8];
    const float* W_e1   = (const float*)d_in[9];
    const float* b_e1   = (const float*)d_in[10];
    const float* ge1    = (const float*)d_in[11];
    const float* bee1   = (const float*)d_in[12];
    const float* W_e2   = (const float*)d_in[13];
    const float* b_e2   = (const float*)d_in[14];
    float* out = (float*)d_out;

    void *p_pp, *p_hp, *p_sp, *p_a, *p_hf;
    void *p_wg_hi, *p_wg_lo, *p_we1_hi, *p_we1_lo, *p_we2_hi, *p_we2_lo;
    cudaGetSymbolAddress(&p_pp, g_parts_part);
    cudaGetSymbolAddress(&p_hp, g_h_part);
    cudaGetSymbolAddress(&p_sp, g_stats_part);
    cudaGetSymbolAddress(&p_a, g_xh_f16);
    cudaGetSymbolAddress(&p_hf, g_h_f16);
    cudaGetSymbolAddress(&p_wg_hi, g_wg_hi);
    cudaGetSymbolAddress(&p_wg_lo, g_wg_lo);
    cudaGetSymbolAddress(&p_we1_hi, g_we1_hi);
    cudaGetSymbolAddress(&p_we1_lo, g_we1_lo);
    cudaGetSymbolAddress(&p_we2_hi, g_we2_hi);
    cudaGetSymbolAddress(&p_we2_lo, g_we2_lo);

    cudaFuncSetAttribute(gemm_hmma, cudaFuncAttributeMaxDynamicSharedMemorySize, SMEM_SZ);

    k_zero<<<512, 256>>>();
    wtrans<<<dim3(3072 / 32, 2048 / 32), dim3(32, 8)>>>(
        W_gru, (__half*)p_wg_hi, (__half*)p_wg_lo, 2048, 3072);
    wtrans<<<dim3(1024 / 32, 1024 / 32), dim3(32, 8)>>>(
        W_e1, (__half*)p_we1_hi, (__half*)p_we1_lo, 1024, 1024);
    wtrans<<<dim3(128 / 32, 1024 / 32), dim3(32, 8)>>>(
        W_e2, (__half*)p_we2_hi, (__half*)p_we2_lo, 1024, 128);

    const dim3 g_gru(3072 / BNT, 2048 / BMT, GRU_SPLITS);  // 24 x 16 x 2
    const dim3 g_e1(1024 / BNT, 2048 / BMT, E1_SPLITS);    //  8 x 16 x 2
    const dim3 g_e2(128 / BNT, 2048 / BMT, E2_SPLITS);     //  1 x 16 x 8
    const int gru_cps = (2048 / 64) / GRU_SPLITS;          // 16
    const int e1_cps  = (1024 / 64) / E1_SPLITS;           // 8
    const int e2_cps  = (1024 / 64) / E2_SPLITS;           // 2

    for (int t = 0; t < NT; t++) {
        k_img<<<NB / IMG_ROWS, 256>>>(action, W_img, b_img, gi, bei, b_e2, out, t);
        gemm_hmma<<<g_gru, 256, SMEM_SZ>>>(
            (__half*)p_a, 2048, 2048,
            (__half*)p_wg_hi, (__half*)p_wg_lo,
            (float*)p_pp, 3072, gru_cps, (long)NB * 3072);
        k_gru<<<NB, 256>>>(b_gru, gg, beg, out, t);
        gemm_hmma<<<g_e1, 256, SMEM_SZ>>>(
            (__half*)p_a + 1024, 2048, 1024,
            (__half*)p_we1_hi, (__half*)p_we1_lo,
            (float*)p_hp, 1024, e1_cps, (long)NB * 1024);
        k_lnelu<<<NB, 256>>>(b_e1, ge1, bee1);
        gemm_hmma<<<g_e2, 256, SMEM_SZ>>>(
            (__half*)p_hf, 1024, 1024,
            (__half*)p_we2_hi, (__half*)p_we2_lo,
            (float*)p_sp, 128, e2_cps, (long)NB * 128);
    }
    k_stats<<<(NB * NSTOCH + 255) / 256, 256>>>(b_e2, out, NT - 1);
    (void)in_sizes; (void)n_in; (void)out_size;
}